// round 13
// baseline (speedup 1.0000x reference)
#include <cuda_runtime.h>
#include <math.h>
#include <stdint.h>

// ---------------------------------------------------------------------------
// Problem constants
// ---------------------------------------------------------------------------
constexpr int EMAX  = 119998;
constexpr int NMAX  = 60000;
constexpr int NEMAX = EMAX / 2;   // 59999

constexpr int W_OFF[7] = {0, 425984, 851968, 1015808, 1277952, 1376256, 1507328};
constexpr int W_TOTAL  = 1769472;

// ---------------------------------------------------------------------------
// Scratch (device globals — no allocation allowed in kernel_launch)
// ---------------------------------------------------------------------------
__device__ float g_feats[(size_t)EMAX * 160];
__device__ float g_suv [(size_t)EMAX * 256];
__device__ float g_zbuf[(size_t)EMAX * 256];
__device__ float g_rbuf[(size_t)EMAX * 256];
__device__ float g_msgA[(size_t)EMAX * 256];
__device__ float g_msgB[(size_t)EMAX * 256];
__device__ float g_aggr[(size_t)NMAX * 256];
__device__ float g_xg  [(size_t)NMAX * 256];
__device__ float g_logits[NMAX + NEMAX];
__device__ float g_wrnd[W_TOTAL];
__device__ float g_wl0[512 * 160];
__device__ float g_bl0[512];

// ---------------------------------------------------------------------------
// TF32 / async helpers
// ---------------------------------------------------------------------------
__device__ __forceinline__ uint32_t f2tf32(float x) {
    uint32_t r;
    asm("cvt.rna.tf32.f32 %0, %1;" : "=r"(r) : "f"(x));
    return r;
}

__device__ __forceinline__ void mma_tf32(float* c, const uint32_t* a,
                                         uint32_t b0, uint32_t b1) {
    asm volatile(
        "mma.sync.aligned.m16n8k8.row.col.f32.tf32.tf32.f32 "
        "{%0,%1,%2,%3}, {%4,%5,%6,%7}, {%8,%9}, {%0,%1,%2,%3};\n"
        : "+f"(c[0]), "+f"(c[1]), "+f"(c[2]), "+f"(c[3])
        : "r"(a[0]), "r"(a[1]), "r"(a[2]), "r"(a[3]),
          "r"(b0), "r"(b1));
}

__device__ __forceinline__ void ldsm_x4(uint32_t* r, uint32_t addr) {
    asm volatile("ldmatrix.sync.aligned.m8n8.x4.shared.b16 {%0,%1,%2,%3}, [%4];\n"
                 : "=r"(r[0]), "=r"(r[1]), "=r"(r[2]), "=r"(r[3]) : "r"(addr));
}

__device__ __forceinline__ void cp_async16(uint32_t saddr, const void* gptr, bool pred) {
    int sz = pred ? 16 : 0;
    asm volatile("cp.async.cg.shared.global [%0], [%1], 16, %2;\n"
                 :: "r"(saddr), "l"(gptr), "r"(sz));
}
__device__ __forceinline__ void cp_commit() {
    asm volatile("cp.async.commit_group;\n" ::: "memory");
}
__device__ __forceinline__ void cp_wait1() {
    asm volatile("cp.async.wait_group 1;\n" ::: "memory");
}

__device__ __forceinline__ float fast_sigmoid(float v) {
    return 1.f / (1.f + __expf(-v));
}
__device__ __forceinline__ float fast_tanh(float v) {
    return 2.f / (1.f + __expf(-2.f * v)) - 1.f;
}

// ---------------------------------------------------------------------------
// 3-stage pipelined TF32 tensor-core GEMM, ldmatrix fragments, 1 sync/iter.
//   C = epi( [A1|A2] @ [W1|W2]^T + bias ),  K1/K2 compile-time (mult of 32).
//   EPI: 0 sigmoid | 1 relu | 2 (1-z)*su + z*tanh(v)
//        5 like 2 but atomicAdd into C[tgt[m]]   (fused segment-sum)
//        6 head: atomicAdd(C[m], sum relu(v)*sb[col])  (fused 512->1 dot)
//        7 layer-0 fused: C[m*256+col/2] = sigmoid(v0)*tanh(v1)
//   GMODE: 0 A2 via cp.async
//          1 A2[m][c] = sum_j msg[nbr[m,j]-1][c]   (fused gather_s; side-write)
//          2 A2[m][c] = sum_j r[..][c]*msg[..][c]  (fused rdash; A2=r, A3=msg)
//          3 whole A from edge pair: [|xg[u]-xg[v]| | xg[u]+xg[v]] (fused xedge)
// BM=BN=128, BK=32, 256 thr, 8 warps (4m x 2n), warp tile 32x64.
// Grid: x = n-block (fast, A L2 reuse), y = m-block.
// ---------------------------------------------------------------------------
constexpr int SK    = 36;
constexpr int TILE  = 128 * SK;
constexpr int STAGE = 2 * TILE;
constexpr int NSTG  = 3;
constexpr int SMEM_BYTES = NSTG * STAGE * 4;   // 110592

template<int EPI, int K1, int K2, int GMODE>
__global__ void __launch_bounds__(256, 2)
gemm_tc(const float* __restrict__ A1,
        const float* __restrict__ A2,
        const float* __restrict__ A3,
        const int* __restrict__ nbrp,
        float* __restrict__ side,
        const float* __restrict__ W1, int ldw1,
        const float* __restrict__ W2, int ldw2,
        const float* __restrict__ bias,
        const float* __restrict__ zb, const float* __restrict__ sb,
        const int* __restrict__ tgt,
        float* __restrict__ C, int M, int Nout, int Epar)
{
    extern __shared__ uint32_t smem[];

    const int tid   = threadIdx.x;
    const int lane  = tid & 31;
    const int wid   = tid >> 5;
    const int warpM = wid & 3;
    const int warpN = wid >> 2;
    const int g     = lane >> 2;
    const int tig   = lane & 3;
    const int m0    = blockIdx.y * 128;
    const int n0    = blockIdx.x * 128;

    const int srow = tid >> 3;
    const int skk  = (tid & 7) << 2;

    const uint32_t smem_base = (uint32_t)__cvta_generic_to_shared(smem);

    // per-thread gather indices (rows fixed for this thread)
    int jj[4][3];
    int eu[4], evv[4];
    if (GMODE == 1 || GMODE == 2) {
#pragma unroll
        for (int r = 0; r < 4; r++) {
            int row = m0 + srow + r * 32;
            if (row >= M) row = M - 1;
            jj[r][0] = nbrp[row * 3 + 0];
            jj[r][1] = nbrp[row * 3 + 1];
            jj[r][2] = nbrp[row * 3 + 2];
        }
    }
    if (GMODE == 3) {
#pragma unroll
        for (int r = 0; r < 4; r++) {
            int row = m0 + srow + r * 32;
            if (row >= M) row = M - 1;
            eu[r]  = nbrp[2 * row];
            evv[r] = nbrp[Epar + 2 * row];
        }
    }

    uint32_t offA[2], offB[4];
    {
        const int ra = (lane & 15);
        const int ca = (lane < 16) ? 0 : 4;
#pragma unroll
        for (int mt = 0; mt < 2; mt++)
            offA[mt] = (uint32_t)(((warpM * 32 + mt * 16 + ra) * SK + ca) * 4);
        const int rb = ((lane & 16) >> 1) + (lane & 7);
        const int cb = (lane & 8) ? 4 : 0;
#pragma unroll
        for (int p = 0; p < 4; p++)
            offB[p] = (uint32_t)(((warpN * 64 + p * 16 + rb) * SK + cb) * 4
                                 + TILE * 4);
    }

    auto stage_tile = [&](int j) {
        const int kk = (j << 5) + skk;
        const int st = (j % NSTG) * STAGE;
        const uint32_t abase = smem_base + (uint32_t)st * 4;
        const uint32_t bbase = abase + (uint32_t)TILE * 4;
#pragma unroll
        for (int r = 0; r < 4; r++) {
            const int rr  = srow + r * 32;
            int row = m0 + rr;
            const bool ok = row < M;
            if (!ok) row = M - 1;
            // ---- A operand ----
            if (GMODE == 3) {
                const int c = (kk < 256) ? kk : (kk - 256);
                float4 a = *(const float4*)(A3 + (size_t)eu[r]  * 256 + c);
                float4 b = *(const float4*)(A3 + (size_t)evv[r] * 256 + c);
                float4 o;
                if (kk < 256) {
                    o.x = fabsf(a.x - b.x); o.y = fabsf(a.y - b.y);
                    o.z = fabsf(a.z - b.z); o.w = fabsf(a.w - b.w);
                } else {
                    o.x = a.x + b.x; o.y = a.y + b.y;
                    o.z = a.z + b.z; o.w = a.w + b.w;
                }
                *(float4*)&smem[st + rr * SK + skk] = o;
            } else if ((GMODE == 1 || GMODE == 2) && kk >= K1) {
                const int c = kk - K1;
                float4 o = make_float4(0.f, 0.f, 0.f, 0.f);
#pragma unroll
                for (int q = 0; q < 3; q++) {
                    const int jx = jj[r][q];
                    if (jx) {
                        const size_t off = (size_t)(jx - 1) * 256 + c;
                        float4 mv = *(const float4*)(A3 + off);
                        if (GMODE == 2) {
                            float4 rv = *(const float4*)(A2 + off);
                            o.x += rv.x * mv.x; o.y += rv.y * mv.y;
                            o.z += rv.z * mv.z; o.w += rv.w * mv.w;
                        } else {
                            o.x += mv.x; o.y += mv.y;
                            o.z += mv.z; o.w += mv.w;
                        }
                    }
                }
                *(float4*)&smem[st + rr * SK + skk] = o;
                if (GMODE == 1 && ok)
                    *(float4*)(side + (size_t)row * 256 + c) = o;
            } else {
                const float* src = (kk < K1)
                    ? A1 + (size_t)row * K1 + kk
                    : A2 + (size_t)row * K2 + (kk - K1);
                cp_async16(abase + (uint32_t)(rr * SK + skk) * 4, src, ok);
            }
            // ---- B operand ----
            const int nn = n0 + rr;
            const float* wsrc = (kk < K1)
                ? W1 + (size_t)nn * ldw1 + kk
                : W2 + (size_t)nn * ldw2 + (kk - K1);
            cp_async16(bbase + (uint32_t)(rr * SK + skk) * 4, wsrc, true);
        }
        cp_commit();
    };

    float acc[2][8][4];
#pragma unroll
    for (int i = 0; i < 2; i++)
#pragma unroll
        for (int j = 0; j < 8; j++)
#pragma unroll
            for (int q = 0; q < 4; q++) acc[i][j][q] = 0.f;

    constexpr int NK = (K1 + K2) >> 5;
    static_assert(NK >= NSTG, "need at least NSTG k-tiles");

    stage_tile(0);
    stage_tile(1);

#pragma unroll
    for (int it = 0; it < NK; it++) {
        cp_wait1();
        __syncthreads();

        if (it + 2 < NK) stage_tile(it + 2);
        else             cp_commit();

        const uint32_t sbase = smem_base + (uint32_t)((it % NSTG) * STAGE) * 4;

#pragma unroll
        for (int ks = 0; ks < 4; ks++) {
            const uint32_t kof = ks * 32;
            uint32_t af[2][4];
            ldsm_x4(af[0], sbase + offA[0] + kof);
            ldsm_x4(af[1], sbase + offA[1] + kof);
            uint32_t bf[4][4];
#pragma unroll
            for (int p = 0; p < 4; p++)
                ldsm_x4(bf[p], sbase + offB[p] + kof);
#pragma unroll
            for (int mt = 0; mt < 2; mt++)
#pragma unroll
                for (int p = 0; p < 4; p++) {
                    mma_tf32(acc[mt][2*p  ], af[mt], bf[p][0], bf[p][1]);
                    mma_tf32(acc[mt][2*p+1], af[mt], bf[p][2], bf[p][3]);
                }
        }
        if (GMODE != 0 && it + 2 < NK) __syncthreads();  // STS vs next ldsm race
    }

    if (EPI == 6) {
        float pr[2][2] = {{0.f, 0.f}, {0.f, 0.f}};
#pragma unroll
        for (int nt = 0; nt < 8; nt++) {
            const int col = n0 + warpN * 64 + nt * 8 + tig * 2;
            const float b0 = bias[col],  b1 = bias[col + 1];
            const float w0 = sb[col],    w1 = sb[col + 1];
#pragma unroll
            for (int mt = 0; mt < 2; mt++)
#pragma unroll
                for (int h = 0; h < 2; h++) {
                    float v0 = acc[mt][nt][h * 2 + 0] + b0;
                    float v1 = acc[mt][nt][h * 2 + 1] + b1;
                    pr[mt][h] += fmaxf(v0, 0.f) * w0 + fmaxf(v1, 0.f) * w1;
                }
        }
#pragma unroll
        for (int mt = 0; mt < 2; mt++)
#pragma unroll
            for (int h = 0; h < 2; h++) {
                pr[mt][h] += __shfl_xor_sync(0xffffffffu, pr[mt][h], 1);
                pr[mt][h] += __shfl_xor_sync(0xffffffffu, pr[mt][h], 2);
            }
        __syncthreads();
        float* red = (float*)smem;
        if (tig == 0) {
#pragma unroll
            for (int mt = 0; mt < 2; mt++)
#pragma unroll
                for (int h = 0; h < 2; h++) {
                    int row = warpM * 32 + mt * 16 + g + h * 8;
                    red[row * 2 + warpN] = pr[mt][h];
                }
        }
        __syncthreads();
        if (warpN == 0 && tig == 0) {
#pragma unroll
            for (int mt = 0; mt < 2; mt++)
#pragma unroll
                for (int h = 0; h < 2; h++) {
                    int row = warpM * 32 + mt * 16 + g + h * 8;
                    int m = m0 + row;
                    if (m < M)
                        atomicAdd(&C[m], red[row * 2] + red[row * 2 + 1]);
                }
        }
        return;
    }

#pragma unroll
    for (int nt = 0; nt < 8; nt++) {
        const int col = n0 + warpN * 64 + nt * 8 + tig * 2;
        const float b0 = bias[col];
        const float b1 = bias[col + 1];
#pragma unroll
        for (int mt = 0; mt < 2; mt++) {
#pragma unroll
            for (int h = 0; h < 2; h++) {
                const int m = m0 + warpM * 32 + mt * 16 + g + h * 8;
                if (m >= M) continue;
                float v0 = acc[mt][nt][h * 2 + 0] + b0;
                float v1 = acc[mt][nt][h * 2 + 1] + b1;
                if (EPI == 7) {
                    C[(size_t)m * 256 + (col >> 1)] =
                        fast_sigmoid(v0) * fast_tanh(v1);
                    continue;
                }
                float2 o;
                if (EPI == 0) {
                    o.x = fast_sigmoid(v0);
                    o.y = fast_sigmoid(v1);
                } else if (EPI == 1) {
                    o.x = fmaxf(v0, 0.f);
                    o.y = fmaxf(v1, 0.f);
                } else {
                    const float2 zz = *(const float2*)(zb + (size_t)m * Nout + col);
                    const float2 su = *(const float2*)(sb + (size_t)m * Nout + col);
                    o.x = (1.f - zz.x) * su.x + zz.x * fast_tanh(v0);
                    o.y = (1.f - zz.y) * su.y + zz.y * fast_tanh(v1);
                }
                if (EPI == 5) {
                    float* dst = C + (size_t)tgt[m] * Nout + col;
                    atomicAdd(dst,     o.x);
                    atomicAdd(dst + 1, o.y);
                } else {
                    *(float2*)(C + (size_t)m * Nout + col) = o;
                }
            }
        }
    }
}

// ---------------------------------------------------------------------------
// Weight prep kernels
// ---------------------------------------------------------------------------
__global__ void roundw_k(const float* __restrict__ s0, const float* __restrict__ s1,
                         const float* __restrict__ s2, const float* __restrict__ s3,
                         const float* __restrict__ s4, const float* __restrict__ s5,
                         const float* __restrict__ s6, float* __restrict__ o)
{
    const int cnt[7] = {425984, 425984, 163840, 262144, 98304, 131072, 262144};
    const int off[7] = {0, 425984, 851968, 1015808, 1277952, 1376256, 1507328};
    const float* srcs[7] = {s0, s1, s2, s3, s4, s5, s6};
    int seg = blockIdx.y;
    int i = (blockIdx.x * blockDim.x + threadIdx.x) * 4;
    if (i >= cnt[seg]) return;
    float4 v = *(const float4*)(srcs[seg] + i);
    float4 r;
    r.x = __uint_as_float(f2tf32(v.x));
    r.y = __uint_as_float(f2tf32(v.y));
    r.z = __uint_as_float(f2tf32(v.z));
    r.w = __uint_as_float(f2tf32(v.w));
    *(float4*)(o + off[seg] + i) = r;
}

__global__ void il0_k(const float* __restrict__ Wz, const float* __restrict__ Ww,
                      const float* __restrict__ Wzb, const float* __restrict__ Ub,
                      float* __restrict__ wo, float* __restrict__ bo)
{
    int t = blockIdx.x * blockDim.x + threadIdx.x;
    if (t < 512) bo[t] = (t & 1) ? Ub[t >> 1] : Wzb[t >> 1];
    if (t >= 512 * 40) return;
    int row = t / 40, c = (t % 40) * 4;
    const float* src = (row & 1)
        ? Ww + (size_t)(row >> 1) * 160 + c
        : Wz + (size_t)(row >> 1) * 416 + c;
    float4 v = *(const float4*)src;
    float4 r;
    r.x = __uint_as_float(f2tf32(v.x));
    r.y = __uint_as_float(f2tf32(v.y));
    r.z = __uint_as_float(f2tf32(v.z));
    r.w = __uint_as_float(f2tf32(v.w));
    *(float4*)(wo + row * 160 + c) = r;
}

__global__ void initlg_k(float* __restrict__ lg, const float* __restrict__ nb,
                         const float* __restrict__ eb, int n, int T)
{
    int t = blockIdx.x * blockDim.x + threadIdx.x;
    if (t >= T) return;
    lg[t] = (t < n) ? nb[0] : eb[0];
}

// ---------------------------------------------------------------------------
// Elementwise kernels
// ---------------------------------------------------------------------------
__global__ void feats_k(const float* __restrict__ x, const float* __restrict__ ea,
                        const int* __restrict__ tgt, float* __restrict__ feats, int E)
{
    int t = blockIdx.x * blockDim.x + threadIdx.x;
    if (t >= E * 40) return;
    int e = t / 40, c = t % 40;
    float4 v;
    if (c < 32) v = *(const float4*)(x + (size_t)tgt[e] * 128 + c * 4);
    else        v = *(const float4*)(ea + (size_t)e * 32 + (c - 32) * 4);
    *(float4*)(feats + (size_t)e * 160 + c * 4) = v;
}

__global__ void softmax_k(const float* __restrict__ lg, float* __restrict__ out, int T)
{
    __shared__ float red[1024];
    int t = threadIdx.x;
    float mx = -1e30f;
    for (int i = t; i < T; i += 1024) mx = fmaxf(mx, lg[i]);
    red[t] = mx; __syncthreads();
    for (int s = 512; s; s >>= 1) { if (t < s) red[t] = fmaxf(red[t], red[t + s]); __syncthreads(); }
    float m = red[0]; __syncthreads();
    float sm = 0.f;
    for (int i = t; i < T; i += 1024) sm += expf(lg[i] - m);
    red[t] = sm; __syncthreads();
    for (int s = 512; s; s >>= 1) { if (t < s) red[t] += red[t + s]; __syncthreads(); }
    float inv = 1.f / red[0];
    for (int i = t; i < T; i += 1024) out[i] = expf(lg[i] - m) * inv;
}

// ---------------------------------------------------------------------------
// Launch — dual-stream DAG; gathers fused into GEMM loaders.
// ---------------------------------------------------------------------------
extern "C" void kernel_launch(void* const* d_in, const int* in_sizes, int n_in,
                              void* d_out, int out_size)
{
    const float* x     = (const float*)d_in[0];
    const float* ea    = (const float*)d_in[1];
    const int*   ei    = (const int*)  d_in[2];
    const int*   nbr   = (const int*)  d_in[3];
    const float* Wz_w  = (const float*)d_in[4];
    const float* Wz_b  = (const float*)d_in[5];
    const float* Wr_w  = (const float*)d_in[6];
    const float* Wr_b  = (const float*)d_in[7];
    const float* W_w   = (const float*)d_in[8];
    const float* U_w   = (const float*)d_in[9];
    const float* U_b   = (const float*)d_in[10];
    const float* mlp_w = (const float*)d_in[11];
    const float* mlp_b = (const float*)d_in[12];
    const float* nc1_w = (const float*)d_in[13];
    const float* nc1_b = (const float*)d_in[14];
    const float* nc2_w = (const float*)d_in[15];
    const float* nc2_b = (const float*)d_in[16];
    const float* ec1_w = (const float*)d_in[17];
    const float* ec1_b = (const float*)d_in[18];
    const float* ec2_w = (const float*)d_in[19];
    const float* ec2_b = (const float*)d_in[20];

    const int n  = in_sizes[0] / 128;
    const int E  = in_sizes[1] / 32;
    const int Ne = E / 2;
    const int* tgt = ei + E;

    float *feats, *suv, *zb, *rb, *msgA, *msgB, *aggr, *xg, *lg, *wr_, *wl0, *bl0;
    cudaGetSymbolAddress((void**)&feats, g_feats);
    cudaGetSymbolAddress((void**)&suv,  g_suv);
    cudaGetSymbolAddress((void**)&zb,   g_zbuf);
    cudaGetSymbolAddress((void**)&rb,   g_rbuf);
    cudaGetSymbolAddress((void**)&msgA, g_msgA);
    cudaGetSymbolAddress((void**)&msgB, g_msgB);
    cudaGetSymbolAddress((void**)&aggr, g_aggr);
    cudaGetSymbolAddress((void**)&xg,   g_xg);
    cudaGetSymbolAddress((void**)&lg,   g_logits);
    cudaGetSymbolAddress((void**)&wr_,  g_wrnd);
    cudaGetSymbolAddress((void**)&wl0,  g_wl0);
    cudaGetSymbolAddress((void**)&bl0,  g_bl0);

    static cudaStream_t s1 = nullptr;
    static cudaEvent_t  ev[16];
    if (!s1) {
        cudaStreamCreateWithFlags(&s1, cudaStreamNonBlocking);
        for (int i = 0; i < 16; i++)
            cudaEventCreateWithFlags(&ev[i], cudaEventDisableTiming);
    }

    cudaFuncSetAttribute(gemm_tc<0,160,256,0>, cudaFuncAttributeMaxDynamicSharedMemorySize, SMEM_BYTES);
    cudaFuncSetAttribute(gemm_tc<0,160,256,1>, cudaFuncAttributeMaxDynamicSharedMemorySize, SMEM_BYTES);
    cudaFuncSetAttribute(gemm_tc<2,160,256,2>, cudaFuncAttributeMaxDynamicSharedMemorySize, SMEM_BYTES);
    cudaFuncSetAttribute(gemm_tc<5,160,256,2>, cudaFuncAttributeMaxDynamicSharedMemorySize, SMEM_BYTES);
    cudaFuncSetAttribute(gemm_tc<7,160,0,0>,   cudaFuncAttributeMaxDynamicSharedMemorySize, SMEM_BYTES);
    cudaFuncSetAttribute(gemm_tc<1,128,256,0>, cudaFuncAttributeMaxDynamicSharedMemorySize, SMEM_BYTES);
    cudaFuncSetAttribute(gemm_tc<6,256,0,0>,   cudaFuncAttributeMaxDynamicSharedMemorySize, SMEM_BYTES);
    cudaFuncSetAttribute(gemm_tc<6,512,0,3>,   cudaFuncAttributeMaxDynamicSharedMemorySize, SMEM_BYTES);

    const float* rWz  = wr_ + W_OFF[0];
    const float* rWr  = wr_ + W_OFF[1];
    const float* rW   = wr_ + W_OFF[2];
    const float* rU   = wr_ + W_OFF[3];
    const float* rmlp = wr_ + W_OFF[4];
    const float* rnc1 = wr_ + W_OFF[5];
    const float* rec1 = wr_ + W_OFF[6];

    const int TPB = 256;
    dim3 gg(2, (E + 127) / 128);

    // ---- prologue: fork first, then s1 work ----
    cudaEventRecord(ev[0], 0);
    cudaStreamWaitEvent(s1, ev[0], 0);
    roundw_k<<<dim3(416, 7), 256, 0, s1>>>(Wz_w, Wr_w, W_w, U_w, mlp_w, nc1_w, ec1_w, wr_);
    il0_k<<<80, 256, 0, s1>>>(Wz_w, W_w, Wz_b, U_b, wl0, bl0);
    cudaEventRecord(ev[1], s1);

    feats_k<<<(E * 40 + TPB - 1) / TPB, TPB>>>(x, ea, tgt, feats, E);
    cudaMemsetAsync(aggr, 0, (size_t)n * 256 * sizeof(float));
    initlg_k<<<(n + Ne + TPB - 1) / TPB, TPB>>>(lg, nc2_b, ec2_b, n, n + Ne);

    cudaStreamWaitEvent(0, ev[1], 0);

    // ---- layer 0: ONE fused GEMM (interleaved z/m columns) ----
    dim3 gl0(4, (E + 127) / 128);
    gemm_tc<7,160,0,0><<<gl0, 256, SMEM_BYTES>>>(
        feats, nullptr, nullptr, nullptr, nullptr, wl0, 160, nullptr, 0,
        bl0, nullptr, nullptr, nullptr, msgA, E, 512, 0);
    cudaEventRecord(ev[2], 0);
    cudaStreamWaitEvent(s1, ev[2], 0);

    float* msg_in  = msgA;
    float* msg_out = msgB;
    int ie = 3;
    for (int l = 1; l < 4; l++) {
        const float* wz = rWz + (size_t)l * 256 * 416;
        const float* wrr= rWr + (size_t)l * 256 * 416;
        const float* ww = rW  + (size_t)l * 256 * 160;
        const float* uw = rU  + (size_t)l * 256 * 256;

        // s1: r-gemm (plain)
        gemm_tc<0,160,256,0><<<gg, 256, SMEM_BYTES, s1>>>(
            feats, msg_in, nullptr, nullptr, nullptr, wrr, 416, wrr + 160, 416,
            Wr_b + l * 256, nullptr, nullptr, nullptr, rb, E, 256, 0);
        cudaEventRecord(ev[ie], s1);

        // s0: z-gemm with fused gather (computes + side-writes suv)
        gemm_tc<0,160,256,1><<<gg, 256, SMEM_BYTES>>>(
            feats, nullptr, msg_in, nbr, suv, wz, 416, wz + 160, 416,
            Wz_b + l * 256, nullptr, nullptr, nullptr, zb, E, 256, 0);

        // join: m-gemm with fused rdash (A2=r, A3=msg)
        cudaStreamWaitEvent(0, ev[ie], 0); ie++;
        if (l < 3) {
            gemm_tc<2,160,256,2><<<gg, 256, SMEM_BYTES>>>(
                feats, rb, msg_in, nbr, nullptr, ww, 160, uw, 256,
                U_b + l * 256, zb, suv, nullptr, msg_out, E, 256, 0);
        } else {
            gemm_tc<5,160,256,2><<<gg, 256, SMEM_BYTES>>>(
                feats, rb, msg_in, nbr, nullptr, ww, 160, uw, 256,
                U_b + l * 256, zb, suv, tgt, aggr, E, 256, 0);
        }
        cudaEventRecord(ev[ie], 0);
        cudaStreamWaitEvent(s1, ev[ie], 0); ie++;

        float* tmp = msg_in; msg_in = msg_out; msg_out = tmp;
    }

    // ---- readout: node head (s0) || edge head (s1) ----
    dim3 gx(2, (n + 127) / 128);
    gemm_tc<1,128,256,0><<<gx, 256, SMEM_BYTES>>>(
        x, aggr, nullptr, nullptr, nullptr, rmlp, 384, rmlp + 128, 384,
        mlp_b, nullptr, nullptr, nullptr, xg, n, 256, 0);
    cudaEventRecord(ev[ie], 0);
    cudaStreamWaitEvent(s1, ev[ie], 0); ie++;

    // s1: edge head with fused xedge (A built from xg[u], xg[v])
    dim3 g2(4, (Ne + 127) / 128);
    gemm_tc<6,512,0,3><<<g2, 256, SMEM_BYTES, s1>>>(
        nullptr, nullptr, xg, ei, nullptr, rec1, 512, nullptr, 0,
        ec1_b, nullptr, ec2_w, nullptr, lg + n, Ne, 512, E);
    cudaEventRecord(ev[ie], s1);

    // s0: node head (fused 512->1 dot into logits)
    dim3 g1(4, (n + 127) / 128);
    gemm_tc<6,256,0,0><<<g1, 256, SMEM_BYTES>>>(
        xg, nullptr, nullptr, nullptr, nullptr, rnc1, 256, nullptr, 0,
        nc1_b, nullptr, nc2_w, nullptr, lg, n, 512, 0);

    // join + softmax
    cudaStreamWaitEvent(0, ev[ie], 0); ie++;
    softmax_k<<<1, 1024>>>(lg, (float*)d_out, n + Ne);
}

// round 14
// speedup vs baseline: 1.1190x; 1.1190x over previous
#include <cuda_runtime.h>
#include <math.h>
#include <stdint.h>

// ---------------------------------------------------------------------------
// Problem constants
// ---------------------------------------------------------------------------
constexpr int EMAX  = 119998;
constexpr int NMAX  = 60000;
constexpr int NEMAX = EMAX / 2;   // 59999

constexpr int W_OFF[7] = {0, 425984, 851968, 1015808, 1277952, 1376256, 1507328};
constexpr int W_TOTAL  = 1769472;

// ---------------------------------------------------------------------------
// Scratch (device globals — no allocation allowed in kernel_launch)
// ---------------------------------------------------------------------------
__device__ float g_feats[(size_t)EMAX * 160];
__device__ float g_suv [(size_t)EMAX * 256];
__device__ float g_zbuf[(size_t)EMAX * 256];
__device__ float g_rbuf[(size_t)EMAX * 256];
__device__ float g_rd  [(size_t)EMAX * 256];
__device__ float g_msgA[(size_t)EMAX * 256];
__device__ float g_msgB[(size_t)EMAX * 256];
__device__ float g_aggr[(size_t)NMAX * 256];
__device__ float g_xg  [(size_t)NMAX * 256];
__device__ float g_xe  [(size_t)NEMAX * 512];
__device__ float g_logits[NMAX + NEMAX];
__device__ float g_wrnd[W_TOTAL];
__device__ float g_wl0[512 * 160];
__device__ float g_bl0[512];
__device__ float g_wzr[3 * 512 * 672];
__device__ float g_bzr[3 * 512];

// ---------------------------------------------------------------------------
// TF32 / async helpers
// ---------------------------------------------------------------------------
__device__ __forceinline__ uint32_t f2tf32(float x) {
    uint32_t r;
    asm("cvt.rna.tf32.f32 %0, %1;" : "=r"(r) : "f"(x));
    return r;
}

__device__ __forceinline__ void mma_tf32(float* c, const uint32_t* a,
                                         uint32_t b0, uint32_t b1) {
    asm volatile(
        "mma.sync.aligned.m16n8k8.row.col.f32.tf32.tf32.f32 "
        "{%0,%1,%2,%3}, {%4,%5,%6,%7}, {%8,%9}, {%0,%1,%2,%3};\n"
        : "+f"(c[0]), "+f"(c[1]), "+f"(c[2]), "+f"(c[3])
        : "r"(a[0]), "r"(a[1]), "r"(a[2]), "r"(a[3]),
          "r"(b0), "r"(b1));
}

__device__ __forceinline__ void ldsm_x4(uint32_t* r, uint32_t addr) {
    asm volatile("ldmatrix.sync.aligned.m8n8.x4.shared.b16 {%0,%1,%2,%3}, [%4];\n"
                 : "=r"(r[0]), "=r"(r[1]), "=r"(r[2]), "=r"(r[3]) : "r"(addr));
}

__device__ __forceinline__ void cp_async16(uint32_t saddr, const void* gptr, bool pred) {
    int sz = pred ? 16 : 0;
    asm volatile("cp.async.cg.shared.global [%0], [%1], 16, %2;\n"
                 :: "r"(saddr), "l"(gptr), "r"(sz));
}
__device__ __forceinline__ void cp_commit() {
    asm volatile("cp.async.commit_group;\n" ::: "memory");
}
__device__ __forceinline__ void cp_wait1() {
    asm volatile("cp.async.wait_group 1;\n" ::: "memory");
}

__device__ __forceinline__ float fast_sigmoid(float v) {
    return 1.f / (1.f + __expf(-v));
}
__device__ __forceinline__ float fast_tanh(float v) {
    return 2.f / (1.f + __expf(-2.f * v)) - 1.f;
}

// ---------------------------------------------------------------------------
// 3-stage pipelined TF32 tensor-core GEMM, ldmatrix fragments, 1 sync/iter.
//   C = epi( [A1|A2|A3] @ W^T + bias ),  K1/K2/K3 compile-time (mult of 32).
//   EPI: 0 sigmoid | 1 relu | 2 (1-z)*su + z*tanh(v)
//        5 like 2 but atomicAdd into C[tgt[m]]   (fused segment-sum)
//        6 head: atomicAdd(C[m], sum relu(v)*sb[col])  (fused 512->1 dot)
//        7 layer-0 fused: C[m*256+col/2] = sigmoid(v0)*tanh(v1)
//        8 zr fused: C[m*256+col/2]=sigmoid(v0), side[m*256+col/2]=sigmoid(v1)
// BM=BN=128, BK=32, 256 thr, 8 warps (4m x 2n), warp tile 32x64.
// Grid: x = n-block (fast, A L2 reuse), y = m-block.
// ---------------------------------------------------------------------------
constexpr int SK    = 36;
constexpr int TILE  = 128 * SK;
constexpr int STAGE = 2 * TILE;
constexpr int NSTG  = 3;
constexpr int SMEM_BYTES = NSTG * STAGE * 4;   // 110592

template<int EPI, int K1, int K2, int K3>
__global__ void __launch_bounds__(256, 2)
gemm_tc(const float* __restrict__ A1,
        const float* __restrict__ A2,
        const float* __restrict__ A3,
        const float* __restrict__ W1, int ldw1,
        const float* __restrict__ W2, int ldw2,
        const float* __restrict__ bias,
        const float* __restrict__ zb, const float* __restrict__ sb,
        const int* __restrict__ tgt,
        float* __restrict__ side,
        float* __restrict__ C, int M, int Nout)
{
    extern __shared__ uint32_t smem[];

    const int tid   = threadIdx.x;
    const int lane  = tid & 31;
    const int wid   = tid >> 5;
    const int warpM = wid & 3;
    const int warpN = wid >> 2;
    const int g     = lane >> 2;
    const int tig   = lane & 3;
    const int m0    = blockIdx.y * 128;
    const int n0    = blockIdx.x * 128;

    const int srow = tid >> 3;
    const int skk  = (tid & 7) << 2;

    const uint32_t smem_base = (uint32_t)__cvta_generic_to_shared(smem);

    uint32_t offA[2], offB[4];
    {
        const int ra = (lane & 15);
        const int ca = (lane < 16) ? 0 : 4;
#pragma unroll
        for (int mt = 0; mt < 2; mt++)
            offA[mt] = (uint32_t)(((warpM * 32 + mt * 16 + ra) * SK + ca) * 4);
        const int rb = ((lane & 16) >> 1) + (lane & 7);
        const int cb = (lane & 8) ? 4 : 0;
#pragma unroll
        for (int p = 0; p < 4; p++)
            offB[p] = (uint32_t)(((warpN * 64 + p * 16 + rb) * SK + cb) * 4
                                 + TILE * 4);
    }

    auto stage_tile = [&](int j) {
        const int kk = (j << 5) + skk;
        const uint32_t abase = smem_base + (uint32_t)((j % NSTG) * STAGE) * 4;
        const uint32_t bbase = abase + (uint32_t)TILE * 4;
#pragma unroll
        for (int r = 0; r < 4; r++) {
            const int rr  = srow + r * 32;
            int row = m0 + rr;
            bool ok = row < M;
            if (!ok) row = M - 1;
            const float* src;
            if (kk < K1)                      src = A1 + (size_t)row * K1 + kk;
            else if (K3 == 0 || kk < K1 + K2) src = A2 + (size_t)row * K2 + (kk - K1);
            else                              src = A3 + (size_t)row * K3 + (kk - K1 - K2);
            cp_async16(abase + (uint32_t)(rr * SK + skk) * 4, src, ok);
            const int nn = n0 + rr;
            const float* wsrc = (kk < K1)
                ? W1 + (size_t)nn * ldw1 + kk
                : W2 + (size_t)nn * ldw2 + (kk - K1);
            cp_async16(bbase + (uint32_t)(rr * SK + skk) * 4, wsrc, true);
        }
        cp_commit();
    };

    float acc[2][8][4];
#pragma unroll
    for (int i = 0; i < 2; i++)
#pragma unroll
        for (int j = 0; j < 8; j++)
#pragma unroll
            for (int q = 0; q < 4; q++) acc[i][j][q] = 0.f;

    constexpr int NK = (K1 + K2 + K3) >> 5;
    static_assert(NK >= NSTG, "need at least NSTG k-tiles");

    stage_tile(0);
    stage_tile(1);

#pragma unroll
    for (int it = 0; it < NK; it++) {
        cp_wait1();
        __syncthreads();

        if (it + 2 < NK) stage_tile(it + 2);
        else             cp_commit();

        const uint32_t sbase = smem_base + (uint32_t)((it % NSTG) * STAGE) * 4;

#pragma unroll
        for (int ks = 0; ks < 4; ks++) {
            const uint32_t kof = ks * 32;
            uint32_t af[2][4];
            ldsm_x4(af[0], sbase + offA[0] + kof);
            ldsm_x4(af[1], sbase + offA[1] + kof);
            uint32_t bf[4][4];
#pragma unroll
            for (int p = 0; p < 4; p++)
                ldsm_x4(bf[p], sbase + offB[p] + kof);
#pragma unroll
            for (int mt = 0; mt < 2; mt++)
#pragma unroll
                for (int p = 0; p < 4; p++) {
                    mma_tf32(acc[mt][2*p  ], af[mt], bf[p][0], bf[p][1]);
                    mma_tf32(acc[mt][2*p+1], af[mt], bf[p][2], bf[p][3]);
                }
        }
    }

    if (EPI == 6) {
        float pr[2][2] = {{0.f, 0.f}, {0.f, 0.f}};
#pragma unroll
        for (int nt = 0; nt < 8; nt++) {
            const int col = n0 + warpN * 64 + nt * 8 + tig * 2;
            const float b0 = bias[col],  b1 = bias[col + 1];
            const float w0 = sb[col],    w1 = sb[col + 1];
#pragma unroll
            for (int mt = 0; mt < 2; mt++)
#pragma unroll
                for (int h = 0; h < 2; h++) {
                    float v0 = acc[mt][nt][h * 2 + 0] + b0;
                    float v1 = acc[mt][nt][h * 2 + 1] + b1;
                    pr[mt][h] += fmaxf(v0, 0.f) * w0 + fmaxf(v1, 0.f) * w1;
                }
        }
#pragma unroll
        for (int mt = 0; mt < 2; mt++)
#pragma unroll
            for (int h = 0; h < 2; h++) {
                pr[mt][h] += __shfl_xor_sync(0xffffffffu, pr[mt][h], 1);
                pr[mt][h] += __shfl_xor_sync(0xffffffffu, pr[mt][h], 2);
            }
        __syncthreads();
        float* red = (float*)smem;
        if (tig == 0) {
#pragma unroll
            for (int mt = 0; mt < 2; mt++)
#pragma unroll
                for (int h = 0; h < 2; h++) {
                    int row = warpM * 32 + mt * 16 + g + h * 8;
                    red[row * 2 + warpN] = pr[mt][h];
                }
        }
        __syncthreads();
        if (warpN == 0 && tig == 0) {
#pragma unroll
            for (int mt = 0; mt < 2; mt++)
#pragma unroll
                for (int h = 0; h < 2; h++) {
                    int row = warpM * 32 + mt * 16 + g + h * 8;
                    int m = m0 + row;
                    if (m < M)
                        atomicAdd(&C[m], red[row * 2] + red[row * 2 + 1]);
                }
        }
        return;
    }

#pragma unroll
    for (int nt = 0; nt < 8; nt++) {
        const int col = n0 + warpN * 64 + nt * 8 + tig * 2;
        const float b0 = bias[col];
        const float b1 = bias[col + 1];
#pragma unroll
        for (int mt = 0; mt < 2; mt++) {
#pragma unroll
            for (int h = 0; h < 2; h++) {
                const int m = m0 + warpM * 32 + mt * 16 + g + h * 8;
                if (m >= M) continue;
                float v0 = acc[mt][nt][h * 2 + 0] + b0;
                float v1 = acc[mt][nt][h * 2 + 1] + b1;
                if (EPI == 7) {
                    C[(size_t)m * 256 + (col >> 1)] =
                        fast_sigmoid(v0) * fast_tanh(v1);
                    continue;
                }
                if (EPI == 8) {
                    C[(size_t)m * 256 + (col >> 1)]    = fast_sigmoid(v0);
                    side[(size_t)m * 256 + (col >> 1)] = fast_sigmoid(v1);
                    continue;
                }
                float2 o;
                if (EPI == 0) {
                    o.x = fast_sigmoid(v0);
                    o.y = fast_sigmoid(v1);
                } else if (EPI == 1) {
                    o.x = fmaxf(v0, 0.f);
                    o.y = fmaxf(v1, 0.f);
                } else {
                    const float2 zz = *(const float2*)(zb + (size_t)m * Nout + col);
                    const float2 su = *(const float2*)(sb + (size_t)m * Nout + col);
                    o.x = (1.f - zz.x) * su.x + zz.x * fast_tanh(v0);
                    o.y = (1.f - zz.y) * su.y + zz.y * fast_tanh(v1);
                }
                if (EPI == 5) {
                    float* dst = C + (size_t)tgt[m] * Nout + col;
                    atomicAdd(dst,     o.x);
                    atomicAdd(dst + 1, o.y);
                } else {
                    *(float2*)(C + (size_t)m * Nout + col) = o;
                }
            }
        }
    }
}

// ---------------------------------------------------------------------------
// Weight prep kernels
// ---------------------------------------------------------------------------
__global__ void roundw_k(const float* __restrict__ s0, const float* __restrict__ s1,
                         const float* __restrict__ s2, const float* __restrict__ s3,
                         const float* __restrict__ s4, const float* __restrict__ s5,
                         const float* __restrict__ s6, float* __restrict__ o)
{
    const int cnt[7] = {425984, 425984, 163840, 262144, 98304, 131072, 262144};
    const int off[7] = {0, 425984, 851968, 1015808, 1277952, 1376256, 1507328};
    const float* srcs[7] = {s0, s1, s2, s3, s4, s5, s6};
    int seg = blockIdx.y;
    int i = (blockIdx.x * blockDim.x + threadIdx.x) * 4;
    if (i >= cnt[seg]) return;
    float4 v = *(const float4*)(srcs[seg] + i);
    float4 r;
    r.x = __uint_as_float(f2tf32(v.x));
    r.y = __uint_as_float(f2tf32(v.y));
    r.z = __uint_as_float(f2tf32(v.z));
    r.w = __uint_as_float(f2tf32(v.w));
    *(float4*)(o + off[seg] + i) = r;
}

__global__ void il0_k(const float* __restrict__ Wz, const float* __restrict__ Ww,
                      const float* __restrict__ Wzb, const float* __restrict__ Ub,
                      float* __restrict__ wo, float* __restrict__ bo)
{
    int t = blockIdx.x * blockDim.x + threadIdx.x;
    if (t < 512) bo[t] = (t & 1) ? Ub[t >> 1] : Wzb[t >> 1];
    if (t >= 512 * 40) return;
    int row = t / 40, c = (t % 40) * 4;
    const float* src = (row & 1)
        ? Ww + (size_t)(row >> 1) * 160 + c
        : Wz + (size_t)(row >> 1) * 416 + c;
    float4 v = *(const float4*)src;
    float4 r;
    r.x = __uint_as_float(f2tf32(v.x));
    r.y = __uint_as_float(f2tf32(v.y));
    r.z = __uint_as_float(f2tf32(v.z));
    r.w = __uint_as_float(f2tf32(v.w));
    *(float4*)(wo + row * 160 + c) = r;
}

// Interleave z/r weights for layers 1..3 into [512 x 672] with zero blocks:
//  row 2j   = [Wz_l[j][0:160] | Wz_l[j][160:416] | 0]
//  row 2j+1 = [Wr_l[j][0:160] | 0 | Wr_l[j][160:416]]
__global__ void ilzr_k(const float* __restrict__ Wz, const float* __restrict__ Wr,
                       const float* __restrict__ Wzb, const float* __restrict__ Wrb,
                       float* __restrict__ wo, float* __restrict__ bo)
{
    int l = blockIdx.y;                 // 0..2 -> layer l+1
    int t = blockIdx.x * blockDim.x + threadIdx.x;
    if (t < 512)
        bo[l * 512 + t] = (t & 1) ? Wrb[(l + 1) * 256 + (t >> 1)]
                                  : Wzb[(l + 1) * 256 + (t >> 1)];
    if (t >= 512 * 168) return;
    int row = t / 168, c = (t % 168) * 4;
    int j = row >> 1;
    const float* src = (row & 1)
        ? Wr + ((size_t)(l + 1) * 256 + j) * 416
        : Wz + ((size_t)(l + 1) * 256 + j) * 416;
    float4 v = make_float4(0.f, 0.f, 0.f, 0.f);
    if (row & 1) {
        if (c < 160)      v = *(const float4*)(src + c);
        else if (c >= 416) v = *(const float4*)(src + 160 + (c - 416));
    } else {
        if (c < 416)      v = *(const float4*)(src + c);
    }
    float4 r;
    r.x = __uint_as_float(f2tf32(v.x));
    r.y = __uint_as_float(f2tf32(v.y));
    r.z = __uint_as_float(f2tf32(v.z));
    r.w = __uint_as_float(f2tf32(v.w));
    *(float4*)(wo + ((size_t)l * 512 + row) * 672 + c) = r;
}

__global__ void initlg_k(float* __restrict__ lg, const float* __restrict__ nb,
                         const float* __restrict__ eb, int n, int T)
{
    int t = blockIdx.x * blockDim.x + threadIdx.x;
    if (t >= T) return;
    lg[t] = (t < n) ? nb[0] : eb[0];
}

// ---------------------------------------------------------------------------
// Elementwise kernels
// ---------------------------------------------------------------------------
__global__ void feats_k(const float* __restrict__ x, const float* __restrict__ ea,
                        const int* __restrict__ tgt, float* __restrict__ feats, int E)
{
    int t = blockIdx.x * blockDim.x + threadIdx.x;
    if (t >= E * 40) return;
    int e = t / 40, c = t % 40;
    float4 v;
    if (c < 32) v = *(const float4*)(x + (size_t)tgt[e] * 128 + c * 4);
    else        v = *(const float4*)(ea + (size_t)e * 32 + (c - 32) * 4);
    *(float4*)(feats + (size_t)e * 160 + c * 4) = v;
}

__global__ void gather_s_k(const float* __restrict__ msg, const int* __restrict__ nbr,
                           float* __restrict__ suv, int E)
{
    int t = blockIdx.x * blockDim.x + threadIdx.x;
    if (t >= E * 64) return;
    int e = t >> 6, c = (t & 63) << 2;
    int j0 = nbr[e*3+0], j1 = nbr[e*3+1], j2 = nbr[e*3+2];
    float ax=0.f, ay=0.f, az=0.f, aw=0.f;
    if (j0) { float4 v = *(const float4*)(msg + (size_t)(j0-1)*256 + c); ax+=v.x; ay+=v.y; az+=v.z; aw+=v.w; }
    if (j1) { float4 v = *(const float4*)(msg + (size_t)(j1-1)*256 + c); ax+=v.x; ay+=v.y; az+=v.z; aw+=v.w; }
    if (j2) { float4 v = *(const float4*)(msg + (size_t)(j2-1)*256 + c); ax+=v.x; ay+=v.y; az+=v.z; aw+=v.w; }
    *(float4*)(suv + (size_t)e * 256 + c) = make_float4(ax, ay, az, aw);
}

__global__ void rdash_k(const float* __restrict__ r, const float* __restrict__ msg,
                        const int* __restrict__ nbr, float* __restrict__ rd, int E)
{
    int t = blockIdx.x * blockDim.x + threadIdx.x;
    if (t >= E * 64) return;
    int e = t >> 6, c = (t & 63) << 2;
    int j0 = nbr[e*3+0], j1 = nbr[e*3+1], j2 = nbr[e*3+2];
    float ax=0.f, ay=0.f, az=0.f, aw=0.f;
    if (j0) { size_t o=(size_t)(j0-1)*256+c; float4 rv=*(const float4*)(r+o); float4 mv=*(const float4*)(msg+o);
              ax+=rv.x*mv.x; ay+=rv.y*mv.y; az+=rv.z*mv.z; aw+=rv.w*mv.w; }
    if (j1) { size_t o=(size_t)(j1-1)*256+c; float4 rv=*(const float4*)(r+o); float4 mv=*(const float4*)(msg+o);
              ax+=rv.x*mv.x; ay+=rv.y*mv.y; az+=rv.z*mv.z; aw+=rv.w*mv.w; }
    if (j2) { size_t o=(size_t)(j2-1)*256+c; float4 rv=*(const float4*)(r+o); float4 mv=*(const float4*)(msg+o);
              ax+=rv.x*mv.x; ay+=rv.y*mv.y; az+=rv.z*mv.z; aw+=rv.w*mv.w; }
    *(float4*)(rd + (size_t)e * 256 + c) = make_float4(ax, ay, az, aw);
}

__global__ void xedge_k(const float* __restrict__ xg, const int* __restrict__ ei,
                        float* __restrict__ xe, int E, int Ne)
{
    int t = blockIdx.x * blockDim.x + threadIdx.x;
    if (t >= Ne * 128) return;
    int j = t >> 7, c = t & 127;
    int u = ei[2 * j], v = ei[E + 2 * j];
    int c2 = (c < 64) ? c : (c - 64);
    float4 a = *(const float4*)(xg + (size_t)u * 256 + c2 * 4);
    float4 b = *(const float4*)(xg + (size_t)v * 256 + c2 * 4);
    float4 o;
    if (c < 64) { o.x=fabsf(a.x-b.x); o.y=fabsf(a.y-b.y); o.z=fabsf(a.z-b.z); o.w=fabsf(a.w-b.w); }
    else        { o.x=a.x+b.x; o.y=a.y+b.y; o.z=a.z+b.z; o.w=a.w+b.w; }
    *(float4*)(xe + (size_t)j * 512 + c * 4) = o;
}

__global__ void softmax_k(const float* __restrict__ lg, float* __restrict__ out, int T)
{
    __shared__ float red[1024];
    int t = threadIdx.x;
    float mx = -1e30f;
    for (int i = t; i < T; i += 1024) mx = fmaxf(mx, lg[i]);
    red[t] = mx; __syncthreads();
    for (int s = 512; s; s >>= 1) { if (t < s) red[t] = fmaxf(red[t], red[t + s]); __syncthreads(); }
    float m = red[0]; __syncthreads();
    float sm = 0.f;
    for (int i = t; i < T; i += 1024) sm += expf(lg[i] - m);
    red[t] = sm; __syncthreads();
    for (int s = 512; s; s >>= 1) { if (t < s) red[t] += red[t + s]; __syncthreads(); }
    float inv = 1.f / red[0];
    for (int i = t; i < T; i += 1024) out[i] = expf(lg[i] - m) * inv;
}

// ---------------------------------------------------------------------------
// Launch — fused zr-GEMM per layer; fused layer-0, seg-sum, head dots.
// ---------------------------------------------------------------------------
extern "C" void kernel_launch(void* const* d_in, const int* in_sizes, int n_in,
                              void* d_out, int out_size)
{
    const float* x     = (const float*)d_in[0];
    const float* ea    = (const float*)d_in[1];
    const int*   ei    = (const int*)  d_in[2];
    const int*   nbr   = (const int*)  d_in[3];
    const float* Wz_w  = (const float*)d_in[4];
    const float* Wz_b  = (const float*)d_in[5];
    const float* Wr_w  = (const float*)d_in[6];
    const float* Wr_b  = (const float*)d_in[7];
    const float* W_w   = (const float*)d_in[8];
    const float* U_w   = (const float*)d_in[9];
    const float* U_b   = (const float*)d_in[10];
    const float* mlp_w = (const float*)d_in[11];
    const float* mlp_b = (const float*)d_in[12];
    const float* nc1_w = (const float*)d_in[13];
    const float* nc1_b = (const float*)d_in[14];
    const float* nc2_w = (const float*)d_in[15];
    const float* nc2_b = (const float*)d_in[16];
    const float* ec1_w = (const float*)d_in[17];
    const float* ec1_b = (const float*)d_in[18];
    const float* ec2_w = (const float*)d_in[19];
    const float* ec2_b = (const float*)d_in[20];

    const int n  = in_sizes[0] / 128;
    const int E  = in_sizes[1] / 32;
    const int Ne = E / 2;
    const int* tgt = ei + E;

    float *feats, *suv, *zb, *rb, *rd, *msgA, *msgB, *aggr, *xg, *xe, *lg;
    float *wr_, *wl0, *bl0, *wzr, *bzr;
    cudaGetSymbolAddress((void**)&feats, g_feats);
    cudaGetSymbolAddress((void**)&suv,  g_suv);
    cudaGetSymbolAddress((void**)&zb,   g_zbuf);
    cudaGetSymbolAddress((void**)&rb,   g_rbuf);
    cudaGetSymbolAddress((void**)&rd,   g_rd);
    cudaGetSymbolAddress((void**)&msgA, g_msgA);
    cudaGetSymbolAddress((void**)&msgB, g_msgB);
    cudaGetSymbolAddress((void**)&aggr, g_aggr);
    cudaGetSymbolAddress((void**)&xg,   g_xg);
    cudaGetSymbolAddress((void**)&xe,   g_xe);
    cudaGetSymbolAddress((void**)&lg,   g_logits);
    cudaGetSymbolAddress((void**)&wr_,  g_wrnd);
    cudaGetSymbolAddress((void**)&wl0,  g_wl0);
    cudaGetSymbolAddress((void**)&bl0,  g_bl0);
    cudaGetSymbolAddress((void**)&wzr,  g_wzr);
    cudaGetSymbolAddress((void**)&bzr,  g_bzr);

    static cudaStream_t s1 = nullptr;
    static cudaEvent_t  ev[16];
    if (!s1) {
        cudaStreamCreateWithFlags(&s1, cudaStreamNonBlocking);
        for (int i = 0; i < 16; i++)
            cudaEventCreateWithFlags(&ev[i], cudaEventDisableTiming);
    }

    cudaFuncSetAttribute(gemm_tc<8,160,256,256>, cudaFuncAttributeMaxDynamicSharedMemorySize, SMEM_BYTES);
    cudaFuncSetAttribute(gemm_tc<2,160,256,0>,   cudaFuncAttributeMaxDynamicSharedMemorySize, SMEM_BYTES);
    cudaFuncSetAttribute(gemm_tc<5,160,256,0>,   cudaFuncAttributeMaxDynamicSharedMemorySize, SMEM_BYTES);
    cudaFuncSetAttribute(gemm_tc<7,160,0,0>,     cudaFuncAttributeMaxDynamicSharedMemorySize, SMEM_BYTES);
    cudaFuncSetAttribute(gemm_tc<1,128,256,0>,   cudaFuncAttributeMaxDynamicSharedMemorySize, SMEM_BYTES);
    cudaFuncSetAttribute(gemm_tc<6,256,0,0>,     cudaFuncAttributeMaxDynamicSharedMemorySize, SMEM_BYTES);
    cudaFuncSetAttribute(gemm_tc<6,512,0,0>,     cudaFuncAttributeMaxDynamicSharedMemorySize, SMEM_BYTES);

    const float* rW   = wr_ + W_OFF[2];
    const float* rU   = wr_ + W_OFF[3];
    const float* rmlp = wr_ + W_OFF[4];
    const float* rnc1 = wr_ + W_OFF[5];
    const float* rec1 = wr_ + W_OFF[6];

    const int TPB = 256;
    const int gE64 = (E * 64 + TPB - 1) / TPB;

    // ---- prologue: fork first, then s1 weight prep ----
    cudaEventRecord(ev[0], 0);
    cudaStreamWaitEvent(s1, ev[0], 0);
    roundw_k<<<dim3(416, 7), 256, 0, s1>>>(Wz_w, Wr_w, W_w, U_w, mlp_w, nc1_w, ec1_w, wr_);
    il0_k<<<80, 256, 0, s1>>>(Wz_w, W_w, Wz_b, U_b, wl0, bl0);
    ilzr_k<<<dim3(336, 3), 256, 0, s1>>>(Wz_w, Wr_w, Wz_b, Wr_b, wzr, bzr);
    cudaEventRecord(ev[1], s1);

    feats_k<<<(E * 40 + TPB - 1) / TPB, TPB>>>(x, ea, tgt, feats, E);
    cudaMemsetAsync(aggr, 0, (size_t)n * 256 * sizeof(float));
    initlg_k<<<(n + Ne + TPB - 1) / TPB, TPB>>>(lg, nc2_b, ec2_b, n, n + Ne);

    cudaStreamWaitEvent(0, ev[1], 0);

    // ---- layer 0: fused z*tanh(m) GEMM ----
    dim3 gl0(4, (E + 127) / 128);
    gemm_tc<7,160,0,0><<<gl0, 256, SMEM_BYTES>>>(
        feats, nullptr, nullptr, wl0, 160, nullptr, 0,
        bl0, nullptr, nullptr, nullptr, nullptr, msgA, E, 512);

    float* msg_in  = msgA;
    float* msg_out = msgB;
    dim3 gg(2, (E + 127) / 128);
    dim3 gzr(4, (E + 127) / 128);
    for (int l = 1; l < 4; l++) {
        const float* wzr_l = wzr + (size_t)(l - 1) * 512 * 672;
        const float* bzr_l = bzr + (l - 1) * 512;
        const float* ww = rW + (size_t)l * 256 * 160;
        const float* uw = rU + (size_t)l * 256 * 256;

        gather_s_k<<<gE64, TPB>>>(msg_in, nbr, suv, E);
        // combined z+r GEMM (interleaved outputs)
        gemm_tc<8,160,256,256><<<gzr, 256, SMEM_BYTES>>>(
            feats, suv, msg_in, wzr_l, 672, wzr_l + 160, 672,
            bzr_l, nullptr, nullptr, nullptr, rb, zb, E, 512);
        rdash_k<<<gE64, TPB>>>(rb, msg_in, nbr, rd, E);
        if (l < 3) {
            gemm_tc<2,160,256,0><<<gg, 256, SMEM_BYTES>>>(
                feats, rd, nullptr, ww, 160, uw, 256,
                U_b + l * 256, zb, suv, nullptr, nullptr, msg_out, E, 256);
        } else {
            gemm_tc<5,160,256,0><<<gg, 256, SMEM_BYTES>>>(
                feats, rd, nullptr, ww, 160, uw, 256,
                U_b + l * 256, zb, suv, tgt, nullptr, aggr, E, 256);
        }
        float* tmp = msg_in; msg_in = msg_out; msg_out = tmp;
    }

    // ---- readout: node head (s0) || edge head (s1) ----
    dim3 gx(2, (n + 127) / 128);
    gemm_tc<1,128,256,0><<<gx, 256, SMEM_BYTES>>>(
        x, aggr, nullptr, rmlp, 384, rmlp + 128, 384,
        mlp_b, nullptr, nullptr, nullptr, nullptr, xg, n, 256);
    cudaEventRecord(ev[2], 0);
    cudaStreamWaitEvent(s1, ev[2], 0);

    // s1: edge branch (xedge + fused 512->1 dot)
    xedge_k<<<(Ne * 128 + TPB - 1) / TPB, TPB, 0, s1>>>(xg, ei, xe, E, Ne);
    dim3 g2(4, (Ne + 127) / 128);
    gemm_tc<6,512,0,0><<<g2, 256, SMEM_BYTES, s1>>>(
        xe, nullptr, nullptr, rec1, 512, nullptr, 0,
        ec1_b, nullptr, ec2_w, nullptr, nullptr, lg + n, Ne, 512);
    cudaEventRecord(ev[3], s1);

    // s0: node branch (fused 512->1 dot)
    dim3 g1(4, (n + 127) / 128);
    gemm_tc<6,256,0,0><<<g1, 256, SMEM_BYTES>>>(
        xg, nullptr, nullptr, rnc1, 256, nullptr, 0,
        nc1_b, nullptr, nc2_w, nullptr, nullptr, lg, n, 512);

    // join + softmax
    cudaStreamWaitEvent(0, ev[3], 0);
    softmax_k<<<1, 1024>>>(lg, (float*)d_out, n + Ne);
}

// round 15
// speedup vs baseline: 1.3652x; 1.2200x over previous
#include <cuda_runtime.h>
#include <math.h>
#include <stdint.h>

// ---------------------------------------------------------------------------
// Problem constants
// ---------------------------------------------------------------------------
constexpr int EMAX  = 119998;
constexpr int NMAX  = 60000;
constexpr int NEMAX = EMAX / 2;   // 59999

constexpr int W_OFF[7] = {0, 425984, 851968, 1015808, 1277952, 1376256, 1507328};
constexpr int W_TOTAL  = 1769472;

// ---------------------------------------------------------------------------
// Scratch (device globals — no allocation allowed in kernel_launch)
// ---------------------------------------------------------------------------
__device__ float g_feats[(size_t)EMAX * 160];
__device__ float g_suv [(size_t)EMAX * 256];
__device__ float g_zbuf[(size_t)EMAX * 256];
__device__ float g_rbuf[(size_t)EMAX * 256];
__device__ float g_rd  [(size_t)EMAX * 256];
__device__ float g_msgA[(size_t)EMAX * 256];
__device__ float g_msgB[(size_t)EMAX * 256];
__device__ float g_aggr[(size_t)NMAX * 256];
__device__ float g_xg  [(size_t)NMAX * 256];
__device__ float g_xe  [(size_t)NEMAX * 512];
__device__ float g_logits[NMAX + NEMAX];
__device__ float g_wrnd[W_TOTAL];
__device__ float g_wl0[512 * 160];
__device__ float g_bl0[512];

// ---------------------------------------------------------------------------
// TF32 / async helpers
// ---------------------------------------------------------------------------
__device__ __forceinline__ uint32_t f2tf32(float x) {
    uint32_t r;
    asm("cvt.rna.tf32.f32 %0, %1;" : "=r"(r) : "f"(x));
    return r;
}

__device__ __forceinline__ void mma_tf32(float* c, const uint32_t* a,
                                         uint32_t b0, uint32_t b1) {
    asm volatile(
        "mma.sync.aligned.m16n8k8.row.col.f32.tf32.tf32.f32 "
        "{%0,%1,%2,%3}, {%4,%5,%6,%7}, {%8,%9}, {%0,%1,%2,%3};\n"
        : "+f"(c[0]), "+f"(c[1]), "+f"(c[2]), "+f"(c[3])
        : "r"(a[0]), "r"(a[1]), "r"(a[2]), "r"(a[3]),
          "r"(b0), "r"(b1));
}

__device__ __forceinline__ void ldsm_x4(uint32_t* r, uint32_t addr) {
    asm volatile("ldmatrix.sync.aligned.m8n8.x4.shared.b16 {%0,%1,%2,%3}, [%4];\n"
                 : "=r"(r[0]), "=r"(r[1]), "=r"(r[2]), "=r"(r[3]) : "r"(addr));
}

__device__ __forceinline__ void cp_async16(uint32_t saddr, const void* gptr, bool pred) {
    int sz = pred ? 16 : 0;
    asm volatile("cp.async.cg.shared.global [%0], [%1], 16, %2;\n"
                 :: "r"(saddr), "l"(gptr), "r"(sz));
}
__device__ __forceinline__ void cp_commit() {
    asm volatile("cp.async.commit_group;\n" ::: "memory");
}
__device__ __forceinline__ void cp_wait1() {
    asm volatile("cp.async.wait_group 1;\n" ::: "memory");
}

__device__ __forceinline__ float fast_sigmoid(float v) {
    return 1.f / (1.f + __expf(-v));
}
__device__ __forceinline__ float fast_tanh(float v) {
    return 2.f / (1.f + __expf(-2.f * v)) - 1.f;
}

// ---------------------------------------------------------------------------
// 3-stage pipelined TF32 tensor-core GEMM, ldmatrix fragments, 1 sync/iter.
//   C = epi( [A1|A2] @ [W1|W2]^T + bias ),  K1/K2 compile-time (mult of 32).
//   EPI: 0 sigmoid | 1 relu | 2 (1-z)*su + z*tanh(v)
//        5 like 2 but atomicAdd into C[tgt[m]]   (fused segment-sum)
//        6 head: atomicAdd(C[m], sum relu(v)*sb[col])  (fused 512->1 dot)
//        7 layer-0 fused: C[m*256+col/2] = sigmoid(v0)*tanh(v1)
// BM=BN=128, BK=32, 256 thr, 8 warps (4m x 2n), warp tile 32x64.
// Grid: x = n-block (fast, A L2 reuse), y = m-block.
// ---------------------------------------------------------------------------
constexpr int SK    = 36;
constexpr int TILE  = 128 * SK;
constexpr int STAGE = 2 * TILE;
constexpr int NSTG  = 3;
constexpr int SMEM_BYTES = NSTG * STAGE * 4;   // 110592

template<int EPI, int K1, int K2>
__global__ void __launch_bounds__(256, 2)
gemm_tc(const float* __restrict__ A1,
        const float* __restrict__ A2,
        const float* __restrict__ W1, int ldw1,
        const float* __restrict__ W2, int ldw2,
        const float* __restrict__ bias,
        const float* __restrict__ zb, const float* __restrict__ sb,
        const int* __restrict__ tgt,
        float* __restrict__ C, int M, int Nout)
{
    extern __shared__ uint32_t smem[];

    const int tid   = threadIdx.x;
    const int lane  = tid & 31;
    const int wid   = tid >> 5;
    const int warpM = wid & 3;
    const int warpN = wid >> 2;
    const int g     = lane >> 2;
    const int tig   = lane & 3;
    const int m0    = blockIdx.y * 128;
    const int n0    = blockIdx.x * 128;

    const int srow = tid >> 3;
    const int skk  = (tid & 7) << 2;

    const uint32_t smem_base = (uint32_t)__cvta_generic_to_shared(smem);

    uint32_t offA[2], offB[4];
    {
        const int ra = (lane & 15);
        const int ca = (lane < 16) ? 0 : 4;
#pragma unroll
        for (int mt = 0; mt < 2; mt++)
            offA[mt] = (uint32_t)(((warpM * 32 + mt * 16 + ra) * SK + ca) * 4);
        const int rb = ((lane & 16) >> 1) + (lane & 7);
        const int cb = (lane & 8) ? 4 : 0;
#pragma unroll
        for (int p = 0; p < 4; p++)
            offB[p] = (uint32_t)(((warpN * 64 + p * 16 + rb) * SK + cb) * 4
                                 + TILE * 4);
    }

    auto stage_tile = [&](int j) {
        const int kk = (j << 5) + skk;
        const uint32_t abase = smem_base + (uint32_t)((j % NSTG) * STAGE) * 4;
        const uint32_t bbase = abase + (uint32_t)TILE * 4;
#pragma unroll
        for (int r = 0; r < 4; r++) {
            const int rr  = srow + r * 32;
            int row = m0 + rr;
            bool ok = row < M;
            if (!ok) row = M - 1;
            const float* src = (kk < K1)
                ? A1 + (size_t)row * K1 + kk
                : A2 + (size_t)row * K2 + (kk - K1);
            cp_async16(abase + (uint32_t)(rr * SK + skk) * 4, src, ok);
            const int nn = n0 + rr;
            const float* wsrc = (kk < K1)
                ? W1 + (size_t)nn * ldw1 + kk
                : W2 + (size_t)nn * ldw2 + (kk - K1);
            cp_async16(bbase + (uint32_t)(rr * SK + skk) * 4, wsrc, true);
        }
        cp_commit();
    };

    float acc[2][8][4];
#pragma unroll
    for (int i = 0; i < 2; i++)
#pragma unroll
        for (int j = 0; j < 8; j++)
#pragma unroll
            for (int q = 0; q < 4; q++) acc[i][j][q] = 0.f;

    constexpr int NK = (K1 + K2) >> 5;
    static_assert(NK >= NSTG, "need at least NSTG k-tiles");

    stage_tile(0);
    stage_tile(1);

#pragma unroll
    for (int it = 0; it < NK; it++) {
        cp_wait1();
        __syncthreads();

        if (it + 2 < NK) stage_tile(it + 2);
        else             cp_commit();

        const uint32_t sbase = smem_base + (uint32_t)((it % NSTG) * STAGE) * 4;

#pragma unroll
        for (int ks = 0; ks < 4; ks++) {
            const uint32_t kof = ks * 32;
            uint32_t af[2][4];
            ldsm_x4(af[0], sbase + offA[0] + kof);
            ldsm_x4(af[1], sbase + offA[1] + kof);
            uint32_t bf[4][4];
#pragma unroll
            for (int p = 0; p < 4; p++)
                ldsm_x4(bf[p], sbase + offB[p] + kof);
#pragma unroll
            for (int mt = 0; mt < 2; mt++)
#pragma unroll
                for (int p = 0; p < 4; p++) {
                    mma_tf32(acc[mt][2*p  ], af[mt], bf[p][0], bf[p][1]);
                    mma_tf32(acc[mt][2*p+1], af[mt], bf[p][2], bf[p][3]);
                }
        }
    }

    if (EPI == 6) {
        float pr[2][2] = {{0.f, 0.f}, {0.f, 0.f}};
#pragma unroll
        for (int nt = 0; nt < 8; nt++) {
            const int col = n0 + warpN * 64 + nt * 8 + tig * 2;
            const float b0 = bias[col],  b1 = bias[col + 1];
            const float w0 = sb[col],    w1 = sb[col + 1];
#pragma unroll
            for (int mt = 0; mt < 2; mt++)
#pragma unroll
                for (int h = 0; h < 2; h++) {
                    float v0 = acc[mt][nt][h * 2 + 0] + b0;
                    float v1 = acc[mt][nt][h * 2 + 1] + b1;
                    pr[mt][h] += fmaxf(v0, 0.f) * w0 + fmaxf(v1, 0.f) * w1;
                }
        }
#pragma unroll
        for (int mt = 0; mt < 2; mt++)
#pragma unroll
            for (int h = 0; h < 2; h++) {
                pr[mt][h] += __shfl_xor_sync(0xffffffffu, pr[mt][h], 1);
                pr[mt][h] += __shfl_xor_sync(0xffffffffu, pr[mt][h], 2);
            }
        __syncthreads();
        float* red = (float*)smem;
        if (tig == 0) {
#pragma unroll
            for (int mt = 0; mt < 2; mt++)
#pragma unroll
                for (int h = 0; h < 2; h++) {
                    int row = warpM * 32 + mt * 16 + g + h * 8;
                    red[row * 2 + warpN] = pr[mt][h];
                }
        }
        __syncthreads();
        if (warpN == 0 && tig == 0) {
#pragma unroll
            for (int mt = 0; mt < 2; mt++)
#pragma unroll
                for (int h = 0; h < 2; h++) {
                    int row = warpM * 32 + mt * 16 + g + h * 8;
                    int m = m0 + row;
                    if (m < M)
                        atomicAdd(&C[m], red[row * 2] + red[row * 2 + 1]);
                }
        }
        return;
    }

#pragma unroll
    for (int nt = 0; nt < 8; nt++) {
        const int col = n0 + warpN * 64 + nt * 8 + tig * 2;
        const float b0 = bias[col];
        const float b1 = bias[col + 1];
#pragma unroll
        for (int mt = 0; mt < 2; mt++) {
#pragma unroll
            for (int h = 0; h < 2; h++) {
                const int m = m0 + warpM * 32 + mt * 16 + g + h * 8;
                if (m >= M) continue;
                float v0 = acc[mt][nt][h * 2 + 0] + b0;
                float v1 = acc[mt][nt][h * 2 + 1] + b1;
                if (EPI == 7) {
                    C[(size_t)m * 256 + (col >> 1)] =
                        fast_sigmoid(v0) * fast_tanh(v1);
                    continue;
                }
                float2 o;
                if (EPI == 0) {
                    o.x = fast_sigmoid(v0);
                    o.y = fast_sigmoid(v1);
                } else if (EPI == 1) {
                    o.x = fmaxf(v0, 0.f);
                    o.y = fmaxf(v1, 0.f);
                } else {
                    const float2 zz = *(const float2*)(zb + (size_t)m * Nout + col);
                    const float2 su = *(const float2*)(sb + (size_t)m * Nout + col);
                    o.x = (1.f - zz.x) * su.x + zz.x * fast_tanh(v0);
                    o.y = (1.f - zz.y) * su.y + zz.y * fast_tanh(v1);
                }
                if (EPI == 5) {
                    float* dst = C + (size_t)tgt[m] * Nout + col;
                    atomicAdd(dst,     o.x);
                    atomicAdd(dst + 1, o.y);
                } else {
                    *(float2*)(C + (size_t)m * Nout + col) = o;
                }
            }
        }
    }
}

// ---------------------------------------------------------------------------
// Weight prep kernels
// ---------------------------------------------------------------------------
__global__ void roundw_k(const float* __restrict__ s0, const float* __restrict__ s1,
                         const float* __restrict__ s2, const float* __restrict__ s3,
                         const float* __restrict__ s4, const float* __restrict__ s5,
                         const float* __restrict__ s6, float* __restrict__ o)
{
    const int cnt[7] = {425984, 425984, 163840, 262144, 98304, 131072, 262144};
    const int off[7] = {0, 425984, 851968, 1015808, 1277952, 1376256, 1507328};
    const float* srcs[7] = {s0, s1, s2, s3, s4, s5, s6};
    int seg = blockIdx.y;
    int i = (blockIdx.x * blockDim.x + threadIdx.x) * 4;
    if (i >= cnt[seg]) return;
    float4 v = *(const float4*)(srcs[seg] + i);
    float4 r;
    r.x = __uint_as_float(f2tf32(v.x));
    r.y = __uint_as_float(f2tf32(v.y));
    r.z = __uint_as_float(f2tf32(v.z));
    r.w = __uint_as_float(f2tf32(v.w));
    *(float4*)(o + off[seg] + i) = r;
}

__global__ void il0_k(const float* __restrict__ Wz, const float* __restrict__ Ww,
                      const float* __restrict__ Wzb, const float* __restrict__ Ub,
                      float* __restrict__ wo, float* __restrict__ bo)
{
    int t = blockIdx.x * blockDim.x + threadIdx.x;
    if (t < 512) bo[t] = (t & 1) ? Ub[t >> 1] : Wzb[t >> 1];
    if (t >= 512 * 40) return;
    int row = t / 40, c = (t % 40) * 4;
    const float* src = (row & 1)
        ? Ww + (size_t)(row >> 1) * 160 + c
        : Wz + (size_t)(row >> 1) * 416 + c;
    float4 v = *(const float4*)src;
    float4 r;
    r.x = __uint_as_float(f2tf32(v.x));
    r.y = __uint_as_float(f2tf32(v.y));
    r.z = __uint_as_float(f2tf32(v.z));
    r.w = __uint_as_float(f2tf32(v.w));
    *(float4*)(wo + row * 160 + c) = r;
}

__global__ void initlg_k(float* __restrict__ lg, const float* __restrict__ nb,
                         const float* __restrict__ eb, int n, int T)
{
    int t = blockIdx.x * blockDim.x + threadIdx.x;
    if (t >= T) return;
    lg[t] = (t < n) ? nb[0] : eb[0];
}

// ---------------------------------------------------------------------------
// Elementwise kernels
// ---------------------------------------------------------------------------
__global__ void feats_k(const float* __restrict__ x, const float* __restrict__ ea,
                        const int* __restrict__ tgt, float* __restrict__ feats, int E)
{
    int t = blockIdx.x * blockDim.x + threadIdx.x;
    if (t >= E * 40) return;
    int e = t / 40, c = t % 40;
    float4 v;
    if (c < 32) v = *(const float4*)(x + (size_t)tgt[e] * 128 + c * 4);
    else        v = *(const float4*)(ea + (size_t)e * 32 + (c - 32) * 4);
    *(float4*)(feats + (size_t)e * 160 + c * 4) = v;
}

// Combined gather: suv[e]=sum msg[nbr]; rd[e]=sum r[nbr]*msg[nbr] (msg read once)
__global__ void grs_k(const float* __restrict__ r, const float* __restrict__ msg,
                      const int* __restrict__ nbr, float* __restrict__ suv,
                      float* __restrict__ rd, int E)
{
    int t = blockIdx.x * blockDim.x + threadIdx.x;
    if (t >= E * 64) return;
    int e = t >> 6, c = (t & 63) << 2;
    int j0 = nbr[e*3+0], j1 = nbr[e*3+1], j2 = nbr[e*3+2];
    float sx=0.f, sy=0.f, sz=0.f, sw=0.f;
    float dx=0.f, dy=0.f, dz=0.f, dw=0.f;
    if (j0) { size_t o=(size_t)(j0-1)*256+c; float4 mv=*(const float4*)(msg+o); float4 rv=*(const float4*)(r+o);
              sx+=mv.x; sy+=mv.y; sz+=mv.z; sw+=mv.w;
              dx+=rv.x*mv.x; dy+=rv.y*mv.y; dz+=rv.z*mv.z; dw+=rv.w*mv.w; }
    if (j1) { size_t o=(size_t)(j1-1)*256+c; float4 mv=*(const float4*)(msg+o); float4 rv=*(const float4*)(r+o);
              sx+=mv.x; sy+=mv.y; sz+=mv.z; sw+=mv.w;
              dx+=rv.x*mv.x; dy+=rv.y*mv.y; dz+=rv.z*mv.z; dw+=rv.w*mv.w; }
    if (j2) { size_t o=(size_t)(j2-1)*256+c; float4 mv=*(const float4*)(msg+o); float4 rv=*(const float4*)(r+o);
              sx+=mv.x; sy+=mv.y; sz+=mv.z; sw+=mv.w;
              dx+=rv.x*mv.x; dy+=rv.y*mv.y; dz+=rv.z*mv.z; dw+=rv.w*mv.w; }
    *(float4*)(suv + (size_t)e * 256 + c) = make_float4(sx, sy, sz, sw);
    *(float4*)(rd  + (size_t)e * 256 + c) = make_float4(dx, dy, dz, dw);
}

__global__ void xedge_k(const float* __restrict__ xg, const int* __restrict__ ei,
                        float* __restrict__ xe, int E, int Ne)
{
    int t = blockIdx.x * blockDim.x + threadIdx.x;
    if (t >= Ne * 128) return;
    int j = t >> 7, c = t & 127;
    int u = ei[2 * j], v = ei[E + 2 * j];
    int c2 = (c < 64) ? c : (c - 64);
    float4 a = *(const float4*)(xg + (size_t)u * 256 + c2 * 4);
    float4 b = *(const float4*)(xg + (size_t)v * 256 + c2 * 4);
    float4 o;
    if (c < 64) { o.x=fabsf(a.x-b.x); o.y=fabsf(a.y-b.y); o.z=fabsf(a.z-b.z); o.w=fabsf(a.w-b.w); }
    else        { o.x=a.x+b.x; o.y=a.y+b.y; o.z=a.z+b.z; o.w=a.w+b.w; }
    *(float4*)(xe + (size_t)j * 512 + c * 4) = o;
}

__global__ void softmax_k(const float* __restrict__ lg, float* __restrict__ out, int T)
{
    __shared__ float red[1024];
    int t = threadIdx.x;
    float mx = -1e30f;
    for (int i = t; i < T; i += 1024) mx = fmaxf(mx, lg[i]);
    red[t] = mx; __syncthreads();
    for (int s = 512; s; s >>= 1) { if (t < s) red[t] = fmaxf(red[t], red[t + s]); __syncthreads(); }
    float m = red[0]; __syncthreads();
    float sm = 0.f;
    for (int i = t; i < T; i += 1024) sm += expf(lg[i] - m);
    red[t] = sm; __syncthreads();
    for (int s = 512; s; s >>= 1) { if (t < s) red[t] += red[t + s]; __syncthreads(); }
    float inv = 1.f / red[0];
    for (int i = t; i < T; i += 1024) out[i] = expf(lg[i] - m) * inv;
}

// ---------------------------------------------------------------------------
// Launch — serial layers (r -> grs -> z -> m), fused l0 / seg-sum / head dots.
// ---------------------------------------------------------------------------
extern "C" void kernel_launch(void* const* d_in, const int* in_sizes, int n_in,
                              void* d_out, int out_size)
{
    const float* x     = (const float*)d_in[0];
    const float* ea    = (const float*)d_in[1];
    const int*   ei    = (const int*)  d_in[2];
    const int*   nbr   = (const int*)  d_in[3];
    const float* Wz_w  = (const float*)d_in[4];
    const float* Wz_b  = (const float*)d_in[5];
    const float* Wr_w  = (const float*)d_in[6];
    const float* Wr_b  = (const float*)d_in[7];
    const float* W_w   = (const float*)d_in[8];
    const float* U_w   = (const float*)d_in[9];
    const float* U_b   = (const float*)d_in[10];
    const float* mlp_w = (const float*)d_in[11];
    const float* mlp_b = (const float*)d_in[12];
    const float* nc1_w = (const float*)d_in[13];
    const float* nc1_b = (const float*)d_in[14];
    const float* nc2_w = (const float*)d_in[15];
    const float* nc2_b = (const float*)d_in[16];
    const float* ec1_w = (const float*)d_in[17];
    const float* ec1_b = (const float*)d_in[18];
    const float* ec2_w = (const float*)d_in[19];
    const float* ec2_b = (const float*)d_in[20];

    const int n  = in_sizes[0] / 128;
    const int E  = in_sizes[1] / 32;
    const int Ne = E / 2;
    const int* tgt = ei + E;

    float *feats, *suv, *zb, *rb, *rd, *msgA, *msgB, *aggr, *xg, *xe, *lg, *wr_, *wl0, *bl0;
    cudaGetSymbolAddress((void**)&feats, g_feats);
    cudaGetSymbolAddress((void**)&suv,  g_suv);
    cudaGetSymbolAddress((void**)&zb,   g_zbuf);
    cudaGetSymbolAddress((void**)&rb,   g_rbuf);
    cudaGetSymbolAddress((void**)&rd,   g_rd);
    cudaGetSymbolAddress((void**)&msgA, g_msgA);
    cudaGetSymbolAddress((void**)&msgB, g_msgB);
    cudaGetSymbolAddress((void**)&aggr, g_aggr);
    cudaGetSymbolAddress((void**)&xg,   g_xg);
    cudaGetSymbolAddress((void**)&xe,   g_xe);
    cudaGetSymbolAddress((void**)&lg,   g_logits);
    cudaGetSymbolAddress((void**)&wr_,  g_wrnd);
    cudaGetSymbolAddress((void**)&wl0,  g_wl0);
    cudaGetSymbolAddress((void**)&bl0,  g_bl0);

    static cudaStream_t s1 = nullptr;
    static cudaEvent_t  ev[16];
    if (!s1) {
        cudaStreamCreateWithFlags(&s1, cudaStreamNonBlocking);
        for (int i = 0; i < 16; i++)
            cudaEventCreateWithFlags(&ev[i], cudaEventDisableTiming);
    }

    cudaFuncSetAttribute(gemm_tc<0,160,256>, cudaFuncAttributeMaxDynamicSharedMemorySize, SMEM_BYTES);
    cudaFuncSetAttribute(gemm_tc<2,160,256>, cudaFuncAttributeMaxDynamicSharedMemorySize, SMEM_BYTES);
    cudaFuncSetAttribute(gemm_tc<5,160,256>, cudaFuncAttributeMaxDynamicSharedMemorySize, SMEM_BYTES);
    cudaFuncSetAttribute(gemm_tc<7,160,0>,   cudaFuncAttributeMaxDynamicSharedMemorySize, SMEM_BYTES);
    cudaFuncSetAttribute(gemm_tc<1,128,256>, cudaFuncAttributeMaxDynamicSharedMemorySize, SMEM_BYTES);
    cudaFuncSetAttribute(gemm_tc<6,256,0>,   cudaFuncAttributeMaxDynamicSharedMemorySize, SMEM_BYTES);
    cudaFuncSetAttribute(gemm_tc<6,512,0>,   cudaFuncAttributeMaxDynamicSharedMemorySize, SMEM_BYTES);

    const float* rWz  = wr_ + W_OFF[0];
    const float* rWr  = wr_ + W_OFF[1];
    const float* rW   = wr_ + W_OFF[2];
    const float* rU   = wr_ + W_OFF[3];
    const float* rmlp = wr_ + W_OFF[4];
    const float* rnc1 = wr_ + W_OFF[5];
    const float* rec1 = wr_ + W_OFF[6];

    const int TPB = 256;
    const int gE64 = (E * 64 + TPB - 1) / TPB;
    dim3 gg(2, (E + 127) / 128);

    // ---- prologue: fork first, then s1 weight prep ----
    cudaEventRecord(ev[0], 0);
    cudaStreamWaitEvent(s1, ev[0], 0);
    roundw_k<<<dim3(416, 7), 256, 0, s1>>>(Wz_w, Wr_w, W_w, U_w, mlp_w, nc1_w, ec1_w, wr_);
    il0_k<<<80, 256, 0, s1>>>(Wz_w, W_w, Wz_b, U_b, wl0, bl0);
    cudaEventRecord(ev[1], s1);

    feats_k<<<(E * 40 + TPB - 1) / TPB, TPB>>>(x, ea, tgt, feats, E);
    cudaMemsetAsync(aggr, 0, (size_t)n * 256 * sizeof(float));
    initlg_k<<<(n + Ne + TPB - 1) / TPB, TPB>>>(lg, nc2_b, ec2_b, n, n + Ne);

    cudaStreamWaitEvent(0, ev[1], 0);

    // ---- layer 0: ONE fused GEMM (interleaved z/m columns) ----
    dim3 gl0(4, (E + 127) / 128);
    gemm_tc<7,160,0><<<gl0, 256, SMEM_BYTES>>>(
        feats, nullptr, wl0, 160, nullptr, 0,
        bl0, nullptr, nullptr, nullptr, msgA, E, 512);

    // ---- layers 1..3: serial r -> grs -> z -> m (streams don't overlap) ----
    float* msg_in  = msgA;
    float* msg_out = msgB;
    for (int l = 1; l < 4; l++) {
        const float* wz = rWz + (size_t)l * 256 * 416;
        const float* wrr= rWr + (size_t)l * 256 * 416;
        const float* ww = rW  + (size_t)l * 256 * 160;
        const float* uw = rU  + (size_t)l * 256 * 256;

        gemm_tc<0,160,256><<<gg, 256, SMEM_BYTES>>>(
            feats, msg_in, wrr, 416, wrr + 160, 416,
            Wr_b + l * 256, nullptr, nullptr, nullptr, rb, E, 256);
        grs_k<<<gE64, TPB>>>(rb, msg_in, nbr, suv, rd, E);
        gemm_tc<0,160,256><<<gg, 256, SMEM_BYTES>>>(
            feats, suv, wz, 416, wz + 160, 416,
            Wz_b + l * 256, nullptr, nullptr, nullptr, zb, E, 256);
        if (l < 3) {
            gemm_tc<2,160,256><<<gg, 256, SMEM_BYTES>>>(
                feats, rd, ww, 160, uw, 256,
                U_b + l * 256, zb, suv, nullptr, msg_out, E, 256);
        } else {
            gemm_tc<5,160,256><<<gg, 256, SMEM_BYTES>>>(
                feats, rd, ww, 160, uw, 256,
                U_b + l * 256, zb, suv, tgt, aggr, E, 256);
        }
        float* tmp = msg_in; msg_in = msg_out; msg_out = tmp;
    }

    // ---- readout ----
    dim3 gx(2, (n + 127) / 128);
    gemm_tc<1,128,256><<<gx, 256, SMEM_BYTES>>>(
        x, aggr, rmlp, 384, rmlp + 128, 384,
        mlp_b, nullptr, nullptr, nullptr, xg, n, 256);
    cudaEventRecord(ev[2], 0);
    cudaStreamWaitEvent(s1, ev[2], 0);

    // s1: edge branch (xedge + fused 512->1 dot)
    xedge_k<<<(Ne * 128 + TPB - 1) / TPB, TPB, 0, s1>>>(xg, ei, xe, E, Ne);
    dim3 g2(4, (Ne + 127) / 128);
    gemm_tc<6,512,0><<<g2, 256, SMEM_BYTES, s1>>>(
        xe, nullptr, rec1, 512, nullptr, 0,
        ec1_b, nullptr, ec2_w, nullptr, lg + n, Ne, 512);
    cudaEventRecord(ev[3], s1);

    // s0: node branch (fused 512->1 dot)
    dim3 g1(4, (n + 127) / 128);
    gemm_tc<6,256,0><<<g1, 256, SMEM_BYTES>>>(
        xg, nullptr, rnc1, 256, nullptr, 0,
        nc1_b, nullptr, nc2_w, nullptr, lg, n, 512);

    // join + softmax
    cudaStreamWaitEvent(0, ev[3], 0);
    softmax_k<<<1, 1024>>>(lg, (float*)d_out, n + Ne);
}

// round 16
// speedup vs baseline: 1.8936x; 1.3870x over previous
#include <cuda_runtime.h>
#include <cuda_fp16.h>
#include <math.h>
#include <stdint.h>

// ---------------------------------------------------------------------------
// Problem constants
// ---------------------------------------------------------------------------
constexpr int EMAX  = 119998;
constexpr int NMAX  = 60000;
constexpr int NEMAX = EMAX / 2;   // 59999

constexpr int W_OFF[7] = {0, 425984, 851968, 1015808, 1277952, 1376256, 1507328};
constexpr int W_TOTAL  = 1769472;

// ---------------------------------------------------------------------------
// Scratch (device globals — no allocation allowed in kernel_launch)
// ---------------------------------------------------------------------------
__device__ __half g_feats[(size_t)EMAX * 160];
__device__ __half g_suv [(size_t)EMAX * 256];
__device__ float  g_zbuf[(size_t)EMAX * 256];     // epilogue-only: keep fp32
__device__ __half g_rbuf[(size_t)EMAX * 256];
__device__ __half g_rd  [(size_t)EMAX * 256];
__device__ __half g_msgA[(size_t)EMAX * 256];
__device__ __half g_msgB[(size_t)EMAX * 256];
__device__ float  g_aggr[(size_t)NMAX * 256];     // fp32 atomic accumulation
__device__ __half g_aggr16[(size_t)NMAX * 256];
__device__ __half g_x16 [(size_t)NMAX * 128];
__device__ __half g_xg  [(size_t)NMAX * 256];
__device__ __half g_xe  [(size_t)NEMAX * 512];
__device__ float  g_logits[NMAX + NEMAX];
__device__ __half g_wrnd[W_TOTAL];
__device__ __half g_wl0[512 * 160];
__device__ float  g_bl0[512];

// ---------------------------------------------------------------------------
// Helpers
// ---------------------------------------------------------------------------
__device__ __forceinline__ void mma_f16(float* c, const uint32_t* a,
                                        uint32_t b0, uint32_t b1) {
    asm volatile(
        "mma.sync.aligned.m16n8k16.row.col.f32.f16.f16.f32 "
        "{%0,%1,%2,%3}, {%4,%5,%6,%7}, {%8,%9}, {%0,%1,%2,%3};\n"
        : "+f"(c[0]), "+f"(c[1]), "+f"(c[2]), "+f"(c[3])
        : "r"(a[0]), "r"(a[1]), "r"(a[2]), "r"(a[3]),
          "r"(b0), "r"(b1));
}

__device__ __forceinline__ void ldsm_x4(uint32_t* r, uint32_t addr) {
    asm volatile("ldmatrix.sync.aligned.m8n8.x4.shared.b16 {%0,%1,%2,%3}, [%4];\n"
                 : "=r"(r[0]), "=r"(r[1]), "=r"(r[2]), "=r"(r[3]) : "r"(addr));
}

__device__ __forceinline__ void cp_async16(uint32_t saddr, const void* gptr, bool pred) {
    int sz = pred ? 16 : 0;
    asm volatile("cp.async.cg.shared.global [%0], [%1], 16, %2;\n"
                 :: "r"(saddr), "l"(gptr), "r"(sz));
}
__device__ __forceinline__ void cp_commit() {
    asm volatile("cp.async.commit_group;\n" ::: "memory");
}
__device__ __forceinline__ void cp_wait1() {
    asm volatile("cp.async.wait_group 1;\n" ::: "memory");
}

__device__ __forceinline__ float fast_sigmoid(float v) {
    return 1.f / (1.f + __expf(-v));
}
__device__ __forceinline__ float fast_tanh(float v) {
    return 2.f / (1.f + __expf(-2.f * v)) - 1.f;
}

__device__ __forceinline__ void ld8h(const __half* p, float* f) {
    uint4 u = *(const uint4*)p;
    const __half2* h = (const __half2*)&u;
#pragma unroll
    for (int i = 0; i < 4; i++) {
        float2 t = __half22float2(h[i]);
        f[2*i] = t.x; f[2*i+1] = t.y;
    }
}
__device__ __forceinline__ void st8h(__half* p, const float* f) {
    uint4 u;
    __half2* h = (__half2*)&u;
#pragma unroll
    for (int i = 0; i < 4; i++)
        h[i] = __floats2half2_rn(f[2*i], f[2*i+1]);
    *(uint4*)p = u;
}

// ---------------------------------------------------------------------------
// 3-stage pipelined FP16 tensor-core GEMM (m16n8k16), fp32 accumulate.
//   C = epi( [A1|A2] @ [W1|W2]^T + bias ),  K1/K2 compile-time (mult of 32).
//   EPI: 0 sigmoid->half | 9 sigmoid->float | 1 relu->half
//        2 (1-z)*su + z*tanh(v) -> half   (zbf fp32, sbh half)
//        5 like 2 but atomicAdd float into Cf[tgt[m]]
//        6 head: atomicAdd(Cf[m], sum relu(v)*sbf[col])
//        7 layer-0: Ch[m*256+col/2] = sigmoid(v0)*tanh(v1)
// BM=BN=128, BK=32 halves, 256 thr, 8 warps (4m x 2n), warp tile 32x64.
// Grid: x = n-block (fast), y = m-block.
// ---------------------------------------------------------------------------
constexpr int SK      = 40;                  // halves per row (32 + 8 pad)
constexpr int TILE_B  = 128 * SK * 2;        // 10240 bytes per matrix/stage
constexpr int STAGE_B = 2 * TILE_B;          // 20480
constexpr int NSTG    = 3;
constexpr int SMEM_BYTES = NSTG * STAGE_B;   // 61440

template<int EPI, int K1, int K2>
__global__ void __launch_bounds__(256, 2)
gemm_tc(const __half* __restrict__ A1,
        const __half* __restrict__ A2,
        const __half* __restrict__ W1, int ldw1,
        const __half* __restrict__ W2, int ldw2,
        const float* __restrict__ bias,
        const float* __restrict__ zbf, const __half* __restrict__ sbh,
        const float* __restrict__ sbf,
        const int* __restrict__ tgt,
        __half* __restrict__ Ch, float* __restrict__ Cf,
        int M, int Nout)
{
    extern __shared__ __align__(16) uint32_t smem[];

    const int tid   = threadIdx.x;
    const int lane  = tid & 31;
    const int wid   = tid >> 5;
    const int warpM = wid & 3;
    const int warpN = wid >> 2;
    const int g     = lane >> 2;
    const int tig   = lane & 3;
    const int m0    = blockIdx.y * 128;
    const int n0    = blockIdx.x * 128;

    const int srow = tid >> 2;           // 0..63
    const int skk  = (tid & 3) << 3;     // 0,8,16,24 halves

    const uint32_t smem_base = (uint32_t)__cvta_generic_to_shared(smem);

    uint32_t offA[2], offB[4];
    {
        const int ra = lane & 15;
        const int ca = (lane & 16) ? 8 : 0;
#pragma unroll
        for (int mt = 0; mt < 2; mt++)
            offA[mt] = (uint32_t)(((warpM * 32 + mt * 16 + ra) * SK + ca) * 2);
#pragma unroll
        for (int p = 0; p < 4; p++)
            offB[p] = (uint32_t)(((warpN * 64 + p * 16 + ra) * SK + ca) * 2
                                 + TILE_B);
    }

    auto stage_tile = [&](int j) {
        const int kk = (j << 5) + skk;
        const uint32_t abase = smem_base + (uint32_t)((j % NSTG) * STAGE_B);
        const uint32_t bbase = abase + (uint32_t)TILE_B;
#pragma unroll
        for (int r = 0; r < 2; r++) {
            const int rr  = srow + r * 64;
            int row = m0 + rr;
            bool ok = row < M;
            if (!ok) row = M - 1;
            const __half* src = (kk < K1)
                ? A1 + (size_t)row * K1 + kk
                : A2 + (size_t)row * K2 + (kk - K1);
            cp_async16(abase + (uint32_t)((rr * SK + skk) * 2), src, ok);
            const int nn = n0 + rr;
            const __half* wsrc = (kk < K1)
                ? W1 + (size_t)nn * ldw1 + kk
                : W2 + (size_t)nn * ldw2 + (kk - K1);
            cp_async16(bbase + (uint32_t)((rr * SK + skk) * 2), wsrc, true);
        }
        cp_commit();
    };

    float acc[2][8][4];
#pragma unroll
    for (int i = 0; i < 2; i++)
#pragma unroll
        for (int j = 0; j < 8; j++)
#pragma unroll
            for (int q = 0; q < 4; q++) acc[i][j][q] = 0.f;

    constexpr int NK = (K1 + K2) >> 5;
    static_assert(NK >= NSTG, "need at least NSTG k-tiles");

    stage_tile(0);
    stage_tile(1);

#pragma unroll
    for (int it = 0; it < NK; it++) {
        cp_wait1();
        __syncthreads();

        if (it + 2 < NK) stage_tile(it + 2);
        else             cp_commit();

        const uint32_t sbase = smem_base + (uint32_t)((it % NSTG) * STAGE_B);

#pragma unroll
        for (int ks = 0; ks < 2; ks++) {
            const uint32_t kof = ks * 32;   // 16 halves * 2 bytes
            uint32_t af[2][4];
            ldsm_x4(af[0], sbase + offA[0] + kof);
            ldsm_x4(af[1], sbase + offA[1] + kof);
            uint32_t bf[4][4];
#pragma unroll
            for (int p = 0; p < 4; p++)
                ldsm_x4(bf[p], sbase + offB[p] + kof);
#pragma unroll
            for (int mt = 0; mt < 2; mt++)
#pragma unroll
                for (int p = 0; p < 4; p++) {
                    mma_f16(acc[mt][2*p  ], af[mt], bf[p][0], bf[p][2]);
                    mma_f16(acc[mt][2*p+1], af[mt], bf[p][1], bf[p][3]);
                }
        }
    }

    if (EPI == 6) {
        float pr[2][2] = {{0.f, 0.f}, {0.f, 0.f}};
#pragma unroll
        for (int nt = 0; nt < 8; nt++) {
            const int col = n0 + warpN * 64 + nt * 8 + tig * 2;
            const float b0 = bias[col],  b1 = bias[col + 1];
            const float w0 = sbf[col],   w1 = sbf[col + 1];
#pragma unroll
            for (int mt = 0; mt < 2; mt++)
#pragma unroll
                for (int h = 0; h < 2; h++) {
                    float v0 = acc[mt][nt][h * 2 + 0] + b0;
                    float v1 = acc[mt][nt][h * 2 + 1] + b1;
                    pr[mt][h] += fmaxf(v0, 0.f) * w0 + fmaxf(v1, 0.f) * w1;
                }
        }
#pragma unroll
        for (int mt = 0; mt < 2; mt++)
#pragma unroll
            for (int h = 0; h < 2; h++) {
                pr[mt][h] += __shfl_xor_sync(0xffffffffu, pr[mt][h], 1);
                pr[mt][h] += __shfl_xor_sync(0xffffffffu, pr[mt][h], 2);
            }
        __syncthreads();
        float* red = (float*)smem;
        if (tig == 0) {
#pragma unroll
            for (int mt = 0; mt < 2; mt++)
#pragma unroll
                for (int h = 0; h < 2; h++) {
                    int row = warpM * 32 + mt * 16 + g + h * 8;
                    red[row * 2 + warpN] = pr[mt][h];
                }
        }
        __syncthreads();
        if (warpN == 0 && tig == 0) {
#pragma unroll
            for (int mt = 0; mt < 2; mt++)
#pragma unroll
                for (int h = 0; h < 2; h++) {
                    int row = warpM * 32 + mt * 16 + g + h * 8;
                    int m = m0 + row;
                    if (m < M)
                        atomicAdd(&Cf[m], red[row * 2] + red[row * 2 + 1]);
                }
        }
        return;
    }

#pragma unroll
    for (int nt = 0; nt < 8; nt++) {
        const int col = n0 + warpN * 64 + nt * 8 + tig * 2;
        const float b0 = bias[col];
        const float b1 = bias[col + 1];
#pragma unroll
        for (int mt = 0; mt < 2; mt++) {
#pragma unroll
            for (int h = 0; h < 2; h++) {
                const int m = m0 + warpM * 32 + mt * 16 + g + h * 8;
                if (m >= M) continue;
                float v0 = acc[mt][nt][h * 2 + 0] + b0;
                float v1 = acc[mt][nt][h * 2 + 1] + b1;
                if (EPI == 7) {
                    Ch[(size_t)m * 256 + (col >> 1)] =
                        __float2half_rn(fast_sigmoid(v0) * fast_tanh(v1));
                    continue;
                }
                if (EPI == 9) {
                    *(float2*)(Cf + (size_t)m * Nout + col) =
                        make_float2(fast_sigmoid(v0), fast_sigmoid(v1));
                    continue;
                }
                float2 o;
                if (EPI == 0) {
                    o.x = fast_sigmoid(v0);
                    o.y = fast_sigmoid(v1);
                } else if (EPI == 1) {
                    o.x = fmaxf(v0, 0.f);
                    o.y = fmaxf(v1, 0.f);
                } else {
                    const float2 zz = *(const float2*)(zbf + (size_t)m * Nout + col);
                    const float2 su =
                        __half22float2(*(const __half2*)(sbh + (size_t)m * Nout + col));
                    o.x = (1.f - zz.x) * su.x + zz.x * fast_tanh(v0);
                    o.y = (1.f - zz.y) * su.y + zz.y * fast_tanh(v1);
                }
                if (EPI == 5) {
                    float* dst = Cf + (size_t)tgt[m] * Nout + col;
                    atomicAdd(dst,     o.x);
                    atomicAdd(dst + 1, o.y);
                } else {
                    *(__half2*)(Ch + (size_t)m * Nout + col) =
                        __floats2half2_rn(o.x, o.y);
                }
            }
        }
    }
}

// ---------------------------------------------------------------------------
// Weight prep: convert all weights to fp16 (rna)
// ---------------------------------------------------------------------------
__global__ void roundw_k(const float* __restrict__ s0, const float* __restrict__ s1,
                         const float* __restrict__ s2, const float* __restrict__ s3,
                         const float* __restrict__ s4, const float* __restrict__ s5,
                         const float* __restrict__ s6, __half* __restrict__ o)
{
    const int cnt[7] = {425984, 425984, 163840, 262144, 98304, 131072, 262144};
    const int off[7] = {0, 425984, 851968, 1015808, 1277952, 1376256, 1507328};
    const float* srcs[7] = {s0, s1, s2, s3, s4, s5, s6};
    int seg = blockIdx.y;
    int i = (blockIdx.x * blockDim.x + threadIdx.x) * 4;
    if (i >= cnt[seg]) return;
    float4 v = *(const float4*)(srcs[seg] + i);
    uint2 u;
    __half2* h = (__half2*)&u;
    h[0] = __floats2half2_rn(v.x, v.y);
    h[1] = __floats2half2_rn(v.z, v.w);
    *(uint2*)(o + off[seg] + i) = u;
}

__global__ void il0_k(const float* __restrict__ Wz, const float* __restrict__ Ww,
                      const float* __restrict__ Wzb, const float* __restrict__ Ub,
                      __half* __restrict__ wo, float* __restrict__ bo)
{
    int t = blockIdx.x * blockDim.x + threadIdx.x;
    if (t < 512) bo[t] = (t & 1) ? Ub[t >> 1] : Wzb[t >> 1];
    if (t >= 512 * 40) return;
    int row = t / 40, c = (t % 40) * 4;
    const float* src = (row & 1)
        ? Ww + (size_t)(row >> 1) * 160 + c
        : Wz + (size_t)(row >> 1) * 416 + c;
    float4 v = *(const float4*)src;
    uint2 u;
    __half2* h = (__half2*)&u;
    h[0] = __floats2half2_rn(v.x, v.y);
    h[1] = __floats2half2_rn(v.z, v.w);
    *(uint2*)(wo + row * 160 + c) = u;
}

__global__ void initlg_k(float* __restrict__ lg, const float* __restrict__ nb,
                         const float* __restrict__ eb, int n, int T)
{
    int t = blockIdx.x * blockDim.x + threadIdx.x;
    if (t >= T) return;
    lg[t] = (t < n) ? nb[0] : eb[0];
}

// generic fp32 -> fp16 (8 elements/thread)
__global__ void f2h_k(const float* __restrict__ src, __half* __restrict__ dst, int n8)
{
    int t = blockIdx.x * blockDim.x + threadIdx.x;
    if (t >= n8) return;
    const float* s = src + (size_t)t * 8;
    float f[8];
#pragma unroll
    for (int i = 0; i < 8; i++) f[i] = s[i];
    st8h(dst + (size_t)t * 8, f);
}

// ---------------------------------------------------------------------------
// Elementwise kernels (fp16 activations)
// ---------------------------------------------------------------------------
__global__ void feats_k(const float* __restrict__ x, const float* __restrict__ ea,
                        const int* __restrict__ tgt, __half* __restrict__ feats, int E)
{
    int t = blockIdx.x * blockDim.x + threadIdx.x;
    if (t >= E * 20) return;
    int e = t / 20, c = t % 20;      // chunk of 8
    const float* s = (c < 16)
        ? x + (size_t)tgt[e] * 128 + c * 8
        : ea + (size_t)e * 32 + (c - 16) * 8;
    float f[8];
#pragma unroll
    for (int i = 0; i < 8; i++) f[i] = s[i];
    st8h(feats + (size_t)e * 160 + c * 8, f);
}

// Combined gather: suv = sum msg[nbr], rd = sum r[nbr]*msg[nbr] (msg read once)
__global__ void grs_k(const __half* __restrict__ r, const __half* __restrict__ msg,
                      const int* __restrict__ nbr, __half* __restrict__ suv,
                      __half* __restrict__ rd, int E)
{
    int t = blockIdx.x * blockDim.x + threadIdx.x;
    if (t >= E * 32) return;
    int e = t >> 5, c = (t & 31) << 3;
    int j0 = nbr[e*3+0], j1 = nbr[e*3+1], j2 = nbr[e*3+2];
    float s[8] = {0,0,0,0,0,0,0,0};
    float d[8] = {0,0,0,0,0,0,0,0};
    float mv[8], rv[8];
    if (j0) { size_t o=(size_t)(j0-1)*256+c; ld8h(msg+o, mv); ld8h(r+o, rv);
#pragma unroll
              for (int i=0;i<8;i++){ s[i]+=mv[i]; d[i]+=rv[i]*mv[i]; } }
    if (j1) { size_t o=(size_t)(j1-1)*256+c; ld8h(msg+o, mv); ld8h(r+o, rv);
#pragma unroll
              for (int i=0;i<8;i++){ s[i]+=mv[i]; d[i]+=rv[i]*mv[i]; } }
    if (j2) { size_t o=(size_t)(j2-1)*256+c; ld8h(msg+o, mv); ld8h(r+o, rv);
#pragma unroll
              for (int i=0;i<8;i++){ s[i]+=mv[i]; d[i]+=rv[i]*mv[i]; } }
    st8h(suv + (size_t)e * 256 + c, s);
    st8h(rd  + (size_t)e * 256 + c, d);
}

__global__ void xedge_k(const __half* __restrict__ xg, const int* __restrict__ ei,
                        __half* __restrict__ xe, int E, int Ne)
{
    int t = blockIdx.x * blockDim.x + threadIdx.x;
    if (t >= Ne * 64) return;
    int j = t >> 6, c = t & 63;      // chunk of 8 within 512
    int u = ei[2 * j], v = ei[E + 2 * j];
    int c2 = (c < 32) ? c : (c - 32);
    float a[8], b[8], o[8];
    ld8h(xg + (size_t)u * 256 + c2 * 8, a);
    ld8h(xg + (size_t)v * 256 + c2 * 8, b);
    if (c < 32) {
#pragma unroll
        for (int i = 0; i < 8; i++) o[i] = fabsf(a[i] - b[i]);
    } else {
#pragma unroll
        for (int i = 0; i < 8; i++) o[i] = a[i] + b[i];
    }
    st8h(xe + (size_t)j * 512 + c * 8, o);
}

__global__ void softmax_k(const float* __restrict__ lg, float* __restrict__ out, int T)
{
    __shared__ float red[1024];
    int t = threadIdx.x;
    float mx = -1e30f;
    for (int i = t; i < T; i += 1024) mx = fmaxf(mx, lg[i]);
    red[t] = mx; __syncthreads();
    for (int s = 512; s; s >>= 1) { if (t < s) red[t] = fmaxf(red[t], red[t + s]); __syncthreads(); }
    float m = red[0]; __syncthreads();
    float sm = 0.f;
    for (int i = t; i < T; i += 1024) sm += expf(lg[i] - m);
    red[t] = sm; __syncthreads();
    for (int s = 512; s; s >>= 1) { if (t < s) red[t] += red[t + s]; __syncthreads(); }
    float inv = 1.f / red[0];
    for (int i = t; i < T; i += 1024) out[i] = expf(lg[i] - m) * inv;
}

// ---------------------------------------------------------------------------
// Launch — fp16 GEMMs; serial layers; fused l0 / seg-sum / head dots.
// ---------------------------------------------------------------------------
extern "C" void kernel_launch(void* const* d_in, const int* in_sizes, int n_in,
                              void* d_out, int out_size)
{
    const float* x     = (const float*)d_in[0];
    const float* ea    = (const float*)d_in[1];
    const int*   ei    = (const int*)  d_in[2];
    const int*   nbr   = (const int*)  d_in[3];
    const float* Wz_w  = (const float*)d_in[4];
    const float* Wz_b  = (const float*)d_in[5];
    const float* Wr_w  = (const float*)d_in[6];
    const float* Wr_b  = (const float*)d_in[7];
    const float* W_w   = (const float*)d_in[8];
    const float* U_w   = (const float*)d_in[9];
    const float* U_b   = (const float*)d_in[10];
    const float* mlp_w = (const float*)d_in[11];
    const float* mlp_b = (const float*)d_in[12];
    const float* nc1_w = (const float*)d_in[13];
    const float* nc1_b = (const float*)d_in[14];
    const float* nc2_w = (const float*)d_in[15];
    const float* nc2_b = (const float*)d_in[16];
    const float* ec1_w = (const float*)d_in[17];
    const float* ec1_b = (const float*)d_in[18];
    const float* ec2_w = (const float*)d_in[19];
    const float* ec2_b = (const float*)d_in[20];

    const int n  = in_sizes[0] / 128;
    const int E  = in_sizes[1] / 32;
    const int Ne = E / 2;
    const int* tgt = ei + E;

    __half *feats, *suv, *rb, *rd, *msgA, *msgB, *aggr16, *x16, *xg, *xe, *wr_, *wl0;
    float *zb, *aggr, *lg, *bl0;
    cudaGetSymbolAddress((void**)&feats,  g_feats);
    cudaGetSymbolAddress((void**)&suv,    g_suv);
    cudaGetSymbolAddress((void**)&zb,     g_zbuf);
    cudaGetSymbolAddress((void**)&rb,     g_rbuf);
    cudaGetSymbolAddress((void**)&rd,     g_rd);
    cudaGetSymbolAddress((void**)&msgA,   g_msgA);
    cudaGetSymbolAddress((void**)&msgB,   g_msgB);
    cudaGetSymbolAddress((void**)&aggr,   g_aggr);
    cudaGetSymbolAddress((void**)&aggr16, g_aggr16);
    cudaGetSymbolAddress((void**)&x16,    g_x16);
    cudaGetSymbolAddress((void**)&xg,     g_xg);
    cudaGetSymbolAddress((void**)&xe,     g_xe);
    cudaGetSymbolAddress((void**)&lg,     g_logits);
    cudaGetSymbolAddress((void**)&wr_,    g_wrnd);
    cudaGetSymbolAddress((void**)&wl0,    g_wl0);
    cudaGetSymbolAddress((void**)&bl0,    g_bl0);

    static cudaStream_t s1 = nullptr;
    static cudaEvent_t  ev[16];
    if (!s1) {
        cudaStreamCreateWithFlags(&s1, cudaStreamNonBlocking);
        for (int i = 0; i < 16; i++)
            cudaEventCreateWithFlags(&ev[i], cudaEventDisableTiming);
    }

    cudaFuncSetAttribute(gemm_tc<0,160,256>, cudaFuncAttributeMaxDynamicSharedMemorySize, SMEM_BYTES);
    cudaFuncSetAttribute(gemm_tc<9,160,256>, cudaFuncAttributeMaxDynamicSharedMemorySize, SMEM_BYTES);
    cudaFuncSetAttribute(gemm_tc<2,160,256>, cudaFuncAttributeMaxDynamicSharedMemorySize, SMEM_BYTES);
    cudaFuncSetAttribute(gemm_tc<5,160,256>, cudaFuncAttributeMaxDynamicSharedMemorySize, SMEM_BYTES);
    cudaFuncSetAttribute(gemm_tc<7,160,0>,   cudaFuncAttributeMaxDynamicSharedMemorySize, SMEM_BYTES);
    cudaFuncSetAttribute(gemm_tc<1,128,256>, cudaFuncAttributeMaxDynamicSharedMemorySize, SMEM_BYTES);
    cudaFuncSetAttribute(gemm_tc<6,256,0>,   cudaFuncAttributeMaxDynamicSharedMemorySize, SMEM_BYTES);
    cudaFuncSetAttribute(gemm_tc<6,512,0>,   cudaFuncAttributeMaxDynamicSharedMemorySize, SMEM_BYTES);

    const __half* rWz  = wr_ + W_OFF[0];
    const __half* rWr  = wr_ + W_OFF[1];
    const __half* rW   = wr_ + W_OFF[2];
    const __half* rU   = wr_ + W_OFF[3];
    const __half* rmlp = wr_ + W_OFF[4];
    const __half* rnc1 = wr_ + W_OFF[5];
    const __half* rec1 = wr_ + W_OFF[6];

    const int TPB = 256;
    dim3 gg(2, (E + 127) / 128);

    // ---- prologue: fork first, then s1 weight prep ----
    cudaEventRecord(ev[0], 0);
    cudaStreamWaitEvent(s1, ev[0], 0);
    roundw_k<<<dim3(416, 7), 256, 0, s1>>>(Wz_w, Wr_w, W_w, U_w, mlp_w, nc1_w, ec1_w, wr_);
    il0_k<<<80, 256, 0, s1>>>(Wz_w, W_w, Wz_b, U_b, wl0, bl0);
    cudaEventRecord(ev[1], s1);

    feats_k<<<(E * 20 + TPB - 1) / TPB, TPB>>>(x, ea, tgt, feats, E);
    f2h_k<<<(n * 16 + TPB - 1) / TPB, TPB>>>(x, x16, n * 16);
    cudaMemsetAsync(aggr, 0, (size_t)n * 256 * sizeof(float));
    initlg_k<<<(n + Ne + TPB - 1) / TPB, TPB>>>(lg, nc2_b, ec2_b, n, n + Ne);

    cudaStreamWaitEvent(0, ev[1], 0);

    // ---- layer 0: ONE fused GEMM (interleaved z/m columns) ----
    dim3 gl0(4, (E + 127) / 128);
    gemm_tc<7,160,0><<<gl0, 256, SMEM_BYTES>>>(
        feats, nullptr, wl0, 160, nullptr, 0,
        bl0, nullptr, nullptr, nullptr, nullptr, msgA, nullptr, E, 512);

    // ---- layers 1..3: serial r -> grs -> z -> m ----
    __half* msg_in  = msgA;
    __half* msg_out = msgB;
    const int gE32 = (E * 32 + TPB - 1) / TPB;
    for (int l = 1; l < 4; l++) {
        const __half* wz = rWz + (size_t)l * 256 * 416;
        const __half* wrr= rWr + (size_t)l * 256 * 416;
        const __half* ww = rW  + (size_t)l * 256 * 160;
        const __half* uw = rU  + (size_t)l * 256 * 256;

        gemm_tc<0,160,256><<<gg, 256, SMEM_BYTES>>>(
            feats, msg_in, wrr, 416, wrr + 160, 416,
            Wr_b + l * 256, nullptr, nullptr, nullptr, nullptr, rb, nullptr, E, 256);
        grs_k<<<gE32, TPB>>>(rb, msg_in, nbr, suv, rd, E);
        gemm_tc<9,160,256><<<gg, 256, SMEM_BYTES>>>(
            feats, suv, wz, 416, wz + 160, 416,
            Wz_b + l * 256, nullptr, nullptr, nullptr, nullptr, nullptr, zb, E, 256);
        if (l < 3) {
            gemm_tc<2,160,256><<<gg, 256, SMEM_BYTES>>>(
                feats, rd, ww, 160, uw, 256,
                U_b + l * 256, zb, suv, nullptr, nullptr, msg_out, nullptr, E, 256);
        } else {
            gemm_tc<5,160,256><<<gg, 256, SMEM_BYTES>>>(
                feats, rd, ww, 160, uw, 256,
                U_b + l * 256, zb, suv, nullptr, tgt, nullptr, aggr, E, 256);
        }
        __half* tmp = msg_in; msg_in = msg_out; msg_out = tmp;
    }

    // ---- readout ----
    f2h_k<<<(n * 32 + TPB - 1) / TPB, TPB>>>(aggr, aggr16, n * 32);
    dim3 gx(2, (n + 127) / 128);
    gemm_tc<1,128,256><<<gx, 256, SMEM_BYTES>>>(
        x16, aggr16, rmlp, 384, rmlp + 128, 384,
        mlp_b, nullptr, nullptr, nullptr, nullptr, xg, nullptr, n, 256);
    cudaEventRecord(ev[2], 0);
    cudaStreamWaitEvent(s1, ev[2], 0);

    // s1: edge branch (xedge + fused 512->1 dot)
    xedge_k<<<(Ne * 64 + TPB - 1) / TPB, TPB, 0, s1>>>(xg, ei, xe, E, Ne);
    dim3 g2(4, (Ne + 127) / 128);
    gemm_tc<6,512,0><<<g2, 256, SMEM_BYTES, s1>>>(
        xe, nullptr, rec1, 512, nullptr, 0,
        ec1_b, nullptr, nullptr, ec2_w, nullptr, nullptr, lg + n, Ne, 512);
    cudaEventRecord(ev[3], s1);

    // s0: node branch (fused 512->1 dot)
    dim3 g1(4, (n + 127) / 128);
    gemm_tc<6,256,0><<<g1, 256, SMEM_BYTES>>>(
        xg, nullptr, rnc1, 256, nullptr, 0,
        nc1_b, nullptr, nullptr, nc2_w, nullptr, nullptr, lg, n, 512);

    // join + softmax
    cudaStreamWaitEvent(0, ev[3], 0);
    softmax_k<<<1, 1024>>>(lg, (float*)d_out, n + Ne);
}

// round 17
// speedup vs baseline: 1.9323x; 1.0204x over previous
#include <cuda_runtime.h>
#include <cuda_fp16.h>
#include <math.h>
#include <stdint.h>

// ---------------------------------------------------------------------------
// Problem constants
// ---------------------------------------------------------------------------
constexpr int EMAX  = 119998;
constexpr int NMAX  = 60000;
constexpr int NEMAX = EMAX / 2;   // 59999

constexpr int W_OFF[7] = {0, 425984, 851968, 1015808, 1277952, 1376256, 1507328};
constexpr int W_TOTAL  = 1769472;

// ---------------------------------------------------------------------------
// Scratch (device globals — no allocation allowed in kernel_launch)
// ---------------------------------------------------------------------------
__device__ __half g_feats[(size_t)EMAX * 160];
__device__ __half g_suv [(size_t)EMAX * 256];
__device__ __half g_zbuf[(size_t)EMAX * 256];
__device__ __half g_rbuf[(size_t)EMAX * 256];
__device__ __half g_rd  [(size_t)EMAX * 256];
__device__ __half g_msgA[(size_t)EMAX * 256];
__device__ __half g_msgB[(size_t)EMAX * 256];
__device__ float  g_aggr[(size_t)NMAX * 256];     // fp32 atomic accumulation
__device__ __half g_aggr16[(size_t)NMAX * 256];
__device__ __half g_x16 [(size_t)NMAX * 128];
__device__ __half g_xg  [(size_t)NMAX * 256];
__device__ __half g_xe  [(size_t)NEMAX * 512];
__device__ float  g_logits[NMAX + NEMAX];
__device__ __half g_wrnd[W_TOTAL];
__device__ __half g_wl0[512 * 160];
__device__ float  g_bl0[512];

// ---------------------------------------------------------------------------
// Helpers
// ---------------------------------------------------------------------------
__device__ __forceinline__ void mma_f16(float* c, const uint32_t* a,
                                        uint32_t b0, uint32_t b1) {
    asm volatile(
        "mma.sync.aligned.m16n8k16.row.col.f32.f16.f16.f32 "
        "{%0,%1,%2,%3}, {%4,%5,%6,%7}, {%8,%9}, {%0,%1,%2,%3};\n"
        : "+f"(c[0]), "+f"(c[1]), "+f"(c[2]), "+f"(c[3])
        : "r"(a[0]), "r"(a[1]), "r"(a[2]), "r"(a[3]),
          "r"(b0), "r"(b1));
}

__device__ __forceinline__ void ldsm_x4(uint32_t* r, uint32_t addr) {
    asm volatile("ldmatrix.sync.aligned.m8n8.x4.shared.b16 {%0,%1,%2,%3}, [%4];\n"
                 : "=r"(r[0]), "=r"(r[1]), "=r"(r[2]), "=r"(r[3]) : "r"(addr));
}

__device__ __forceinline__ void cp_async16(uint32_t saddr, const void* gptr, bool pred) {
    int sz = pred ? 16 : 0;
    asm volatile("cp.async.cg.shared.global [%0], [%1], 16, %2;\n"
                 :: "r"(saddr), "l"(gptr), "r"(sz));
}
__device__ __forceinline__ void cp_commit() {
    asm volatile("cp.async.commit_group;\n" ::: "memory");
}
template<int N>
__device__ __forceinline__ void cp_wait() {
    asm volatile("cp.async.wait_group %0;\n" :: "n"(N) : "memory");
}

__device__ __forceinline__ float fast_sigmoid(float v) {
    return 1.f / (1.f + __expf(-v));
}
__device__ __forceinline__ float fast_tanh(float v) {
    return 2.f / (1.f + __expf(-2.f * v)) - 1.f;
}

__device__ __forceinline__ void ld8h(const __half* p, float* f) {
    uint4 u = *(const uint4*)p;
    const __half2* h = (const __half2*)&u;
#pragma unroll
    for (int i = 0; i < 4; i++) {
        float2 t = __half22float2(h[i]);
        f[2*i] = t.x; f[2*i+1] = t.y;
    }
}
__device__ __forceinline__ void st8h(__half* p, const float* f) {
    uint4 u;
    __half2* h = (__half2*)&u;
#pragma unroll
    for (int i = 0; i < 4; i++)
        h[i] = __floats2half2_rn(f[2*i], f[2*i+1]);
    *(uint4*)p = u;
}

// ---------------------------------------------------------------------------
// 4-stage pipelined FP16 tensor-core GEMM (m16n8k16), fp32 accumulate.
//   C = epi( [A1|A2] @ [W1|W2]^T + bias ),  K1/K2 compile-time (mult of 32).
//   EPI: 0 sigmoid->half | 1 relu->half
//        2 (1-z)*su + z*tanh(v) -> half   (zbh half, sbh half)
//        5 like 2 but atomicAdd float into Cf[tgt[m]]
//        6 head: atomicAdd(Cf[m], sum relu(v)*sbf[col])
//        7 layer-0: Ch[m*256+col/2] = sigmoid(v0)*tanh(v1)
// BM=BN=128, BK=32 halves, 256 thr, 8 warps (4m x 2n), warp tile 32x64.
// Grid: x = n-block (fast), y = m-block.
// ---------------------------------------------------------------------------
constexpr int SK      = 40;                  // halves per row (32 + 8 pad)
constexpr int TILE_B  = 128 * SK * 2;        // 10240 bytes per matrix/stage
constexpr int STAGE_B = 2 * TILE_B;          // 20480
constexpr int NSTG    = 4;
constexpr int SMEM_BYTES = NSTG * STAGE_B;   // 81920

template<int EPI, int K1, int K2>
__global__ void __launch_bounds__(256, 2)
gemm_tc(const __half* __restrict__ A1,
        const __half* __restrict__ A2,
        const __half* __restrict__ W1, int ldw1,
        const __half* __restrict__ W2, int ldw2,
        const float* __restrict__ bias,
        const __half* __restrict__ zbh, const __half* __restrict__ sbh,
        const float* __restrict__ sbf,
        const int* __restrict__ tgt,
        __half* __restrict__ Ch, float* __restrict__ Cf,
        int M, int Nout)
{
    extern __shared__ __align__(16) uint32_t smem[];

    const int tid   = threadIdx.x;
    const int lane  = tid & 31;
    const int wid   = tid >> 5;
    const int warpM = wid & 3;
    const int warpN = wid >> 2;
    const int g     = lane >> 2;
    const int tig   = lane & 3;
    const int m0    = blockIdx.y * 128;
    const int n0    = blockIdx.x * 128;

    const int srow = tid >> 2;           // 0..63
    const int skk  = (tid & 3) << 3;     // 0,8,16,24 halves

    const uint32_t smem_base = (uint32_t)__cvta_generic_to_shared(smem);

    uint32_t offA[2], offB[4];
    {
        const int ra = lane & 15;
        const int ca = (lane & 16) ? 8 : 0;
#pragma unroll
        for (int mt = 0; mt < 2; mt++)
            offA[mt] = (uint32_t)(((warpM * 32 + mt * 16 + ra) * SK + ca) * 2);
#pragma unroll
        for (int p = 0; p < 4; p++)
            offB[p] = (uint32_t)(((warpN * 64 + p * 16 + ra) * SK + ca) * 2
                                 + TILE_B);
    }

    auto stage_tile = [&](int j) {
        const int kk = (j << 5) + skk;
        const uint32_t abase = smem_base + (uint32_t)((j % NSTG) * STAGE_B);
        const uint32_t bbase = abase + (uint32_t)TILE_B;
#pragma unroll
        for (int r = 0; r < 2; r++) {
            const int rr  = srow + r * 64;
            int row = m0 + rr;
            bool ok = row < M;
            if (!ok) row = M - 1;
            const __half* src = (kk < K1)
                ? A1 + (size_t)row * K1 + kk
                : A2 + (size_t)row * K2 + (kk - K1);
            cp_async16(abase + (uint32_t)((rr * SK + skk) * 2), src, ok);
            const int nn = n0 + rr;
            const __half* wsrc = (kk < K1)
                ? W1 + (size_t)nn * ldw1 + kk
                : W2 + (size_t)nn * ldw2 + (kk - K1);
            cp_async16(bbase + (uint32_t)((rr * SK + skk) * 2), wsrc, true);
        }
        cp_commit();
    };

    float acc[2][8][4];
#pragma unroll
    for (int i = 0; i < 2; i++)
#pragma unroll
        for (int j = 0; j < 8; j++)
#pragma unroll
            for (int q = 0; q < 4; q++) acc[i][j][q] = 0.f;

    constexpr int NK = (K1 + K2) >> 5;
    static_assert(NK >= NSTG, "need at least NSTG k-tiles");

    stage_tile(0);
    stage_tile(1);
    stage_tile(2);

#pragma unroll
    for (int it = 0; it < NK; it++) {
        cp_wait<2>();          // stage `it` complete (2 newest may be pending)
        __syncthreads();

        if (it + 3 < NK) stage_tile(it + 3);
        else             cp_commit();

        const uint32_t sbase = smem_base + (uint32_t)((it % NSTG) * STAGE_B);

#pragma unroll
        for (int ks = 0; ks < 2; ks++) {
            const uint32_t kof = ks * 32;   // 16 halves * 2 bytes
            uint32_t af[2][4];
            ldsm_x4(af[0], sbase + offA[0] + kof);
            ldsm_x4(af[1], sbase + offA[1] + kof);
            uint32_t bf[4][4];
#pragma unroll
            for (int p = 0; p < 4; p++)
                ldsm_x4(bf[p], sbase + offB[p] + kof);
#pragma unroll
            for (int mt = 0; mt < 2; mt++)
#pragma unroll
                for (int p = 0; p < 4; p++) {
                    mma_f16(acc[mt][2*p  ], af[mt], bf[p][0], bf[p][2]);
                    mma_f16(acc[mt][2*p+1], af[mt], bf[p][1], bf[p][3]);
                }
        }
    }

    if (EPI == 6) {
        float pr[2][2] = {{0.f, 0.f}, {0.f, 0.f}};
#pragma unroll
        for (int nt = 0; nt < 8; nt++) {
            const int col = n0 + warpN * 64 + nt * 8 + tig * 2;
            const float b0 = bias[col],  b1 = bias[col + 1];
            const float w0 = sbf[col],   w1 = sbf[col + 1];
#pragma unroll
            for (int mt = 0; mt < 2; mt++)
#pragma unroll
                for (int h = 0; h < 2; h++) {
                    float v0 = acc[mt][nt][h * 2 + 0] + b0;
                    float v1 = acc[mt][nt][h * 2 + 1] + b1;
                    pr[mt][h] += fmaxf(v0, 0.f) * w0 + fmaxf(v1, 0.f) * w1;
                }
        }
#pragma unroll
        for (int mt = 0; mt < 2; mt++)
#pragma unroll
            for (int h = 0; h < 2; h++) {
                pr[mt][h] += __shfl_xor_sync(0xffffffffu, pr[mt][h], 1);
                pr[mt][h] += __shfl_xor_sync(0xffffffffu, pr[mt][h], 2);
            }
        __syncthreads();
        float* red = (float*)smem;
        if (tig == 0) {
#pragma unroll
            for (int mt = 0; mt < 2; mt++)
#pragma unroll
                for (int h = 0; h < 2; h++) {
                    int row = warpM * 32 + mt * 16 + g + h * 8;
                    red[row * 2 + warpN] = pr[mt][h];
                }
        }
        __syncthreads();
        if (warpN == 0 && tig == 0) {
#pragma unroll
            for (int mt = 0; mt < 2; mt++)
#pragma unroll
                for (int h = 0; h < 2; h++) {
                    int row = warpM * 32 + mt * 16 + g + h * 8;
                    int m = m0 + row;
                    if (m < M)
                        atomicAdd(&Cf[m], red[row * 2] + red[row * 2 + 1]);
                }
        }
        return;
    }

#pragma unroll
    for (int nt = 0; nt < 8; nt++) {
        const int col = n0 + warpN * 64 + nt * 8 + tig * 2;
        const float b0 = bias[col];
        const float b1 = bias[col + 1];
#pragma unroll
        for (int mt = 0; mt < 2; mt++) {
#pragma unroll
            for (int h = 0; h < 2; h++) {
                const int m = m0 + warpM * 32 + mt * 16 + g + h * 8;
                if (m >= M) continue;
                float v0 = acc[mt][nt][h * 2 + 0] + b0;
                float v1 = acc[mt][nt][h * 2 + 1] + b1;
                if (EPI == 7) {
                    Ch[(size_t)m * 256 + (col >> 1)] =
                        __float2half_rn(fast_sigmoid(v0) * fast_tanh(v1));
                    continue;
                }
                float2 o;
                if (EPI == 0) {
                    o.x = fast_sigmoid(v0);
                    o.y = fast_sigmoid(v1);
                } else if (EPI == 1) {
                    o.x = fmaxf(v0, 0.f);
                    o.y = fmaxf(v1, 0.f);
                } else {
                    const float2 zz =
                        __half22float2(*(const __half2*)(zbh + (size_t)m * Nout + col));
                    const float2 su =
                        __half22float2(*(const __half2*)(sbh + (size_t)m * Nout + col));
                    o.x = (1.f - zz.x) * su.x + zz.x * fast_tanh(v0);
                    o.y = (1.f - zz.y) * su.y + zz.y * fast_tanh(v1);
                }
                if (EPI == 5) {
                    float* dst = Cf + (size_t)tgt[m] * Nout + col;
                    atomicAdd(dst,     o.x);
                    atomicAdd(dst + 1, o.y);
                } else {
                    *(__half2*)(Ch + (size_t)m * Nout + col) =
                        __floats2half2_rn(o.x, o.y);
                }
            }
        }
    }
}

// ---------------------------------------------------------------------------
// Weight prep: convert all weights to fp16 (rna)
// ---------------------------------------------------------------------------
__global__ void roundw_k(const float* __restrict__ s0, const float* __restrict__ s1,
                         const float* __restrict__ s2, const float* __restrict__ s3,
                         const float* __restrict__ s4, const float* __restrict__ s5,
                         const float* __restrict__ s6, __half* __restrict__ o)
{
    const int cnt[7] = {425984, 425984, 163840, 262144, 98304, 131072, 262144};
    const int off[7] = {0, 425984, 851968, 1015808, 1277952, 1376256, 1507328};
    const float* srcs[7] = {s0, s1, s2, s3, s4, s5, s6};
    int seg = blockIdx.y;
    int i = (blockIdx.x * blockDim.x + threadIdx.x) * 4;
    if (i >= cnt[seg]) return;
    float4 v = *(const float4*)(srcs[seg] + i);
    uint2 u;
    __half2* h = (__half2*)&u;
    h[0] = __floats2half2_rn(v.x, v.y);
    h[1] = __floats2half2_rn(v.z, v.w);
    *(uint2*)(o + off[seg] + i) = u;
}

__global__ void il0_k(const float* __restrict__ Wz, const float* __restrict__ Ww,
                      const float* __restrict__ Wzb, const float* __restrict__ Ub,
                      __half* __restrict__ wo, float* __restrict__ bo)
{
    int t = blockIdx.x * blockDim.x + threadIdx.x;
    if (t < 512) bo[t] = (t & 1) ? Ub[t >> 1] : Wzb[t >> 1];
    if (t >= 512 * 40) return;
    int row = t / 40, c = (t % 40) * 4;
    const float* src = (row & 1)
        ? Ww + (size_t)(row >> 1) * 160 + c
        : Wz + (size_t)(row >> 1) * 416 + c;
    float4 v = *(const float4*)src;
    uint2 u;
    __half2* h = (__half2*)&u;
    h[0] = __floats2half2_rn(v.x, v.y);
    h[1] = __floats2half2_rn(v.z, v.w);
    *(uint2*)(wo + row * 160 + c) = u;
}

__global__ void initlg_k(float* __restrict__ lg, const float* __restrict__ nb,
                         const float* __restrict__ eb, int n, int T)
{
    int t = blockIdx.x * blockDim.x + threadIdx.x;
    if (t >= T) return;
    lg[t] = (t < n) ? nb[0] : eb[0];
}

// generic fp32 -> fp16 (8 elements/thread)
__global__ void f2h_k(const float* __restrict__ src, __half* __restrict__ dst, int n8)
{
    int t = blockIdx.x * blockDim.x + threadIdx.x;
    if (t >= n8) return;
    const float* s = src + (size_t)t * 8;
    float f[8];
#pragma unroll
    for (int i = 0; i < 8; i++) f[i] = s[i];
    st8h(dst + (size_t)t * 8, f);
}

// ---------------------------------------------------------------------------
// Elementwise kernels (fp16 activations)
// ---------------------------------------------------------------------------
__global__ void feats_k(const float* __restrict__ x, const float* __restrict__ ea,
                        const int* __restrict__ tgt, __half* __restrict__ feats, int E)
{
    int t = blockIdx.x * blockDim.x + threadIdx.x;
    if (t >= E * 20) return;
    int e = t / 20, c = t % 20;      // chunk of 8
    const float* s = (c < 16)
        ? x + (size_t)tgt[e] * 128 + c * 8
        : ea + (size_t)e * 32 + (c - 16) * 8;
    float f[8];
#pragma unroll
    for (int i = 0; i < 8; i++) f[i] = s[i];
    st8h(feats + (size_t)e * 160 + c * 8, f);
}

// Combined gather: suv = sum msg[nbr], rd = sum r[nbr]*msg[nbr] (msg read once)
__global__ void grs_k(const __half* __restrict__ r, const __half* __restrict__ msg,
                      const int* __restrict__ nbr, __half* __restrict__ suv,
                      __half* __restrict__ rd, int E)
{
    int t = blockIdx.x * blockDim.x + threadIdx.x;
    if (t >= E * 32) return;
    int e = t >> 5, c = (t & 31) << 3;
    int j0 = nbr[e*3+0], j1 = nbr[e*3+1], j2 = nbr[e*3+2];
    float s[8] = {0,0,0,0,0,0,0,0};
    float d[8] = {0,0,0,0,0,0,0,0};
    float mv[8], rv[8];
    if (j0) { size_t o=(size_t)(j0-1)*256+c; ld8h(msg+o, mv); ld8h(r+o, rv);
#pragma unroll
              for (int i=0;i<8;i++){ s[i]+=mv[i]; d[i]+=rv[i]*mv[i]; } }
    if (j1) { size_t o=(size_t)(j1-1)*256+c; ld8h(msg+o, mv); ld8h(r+o, rv);
#pragma unroll
              for (int i=0;i<8;i++){ s[i]+=mv[i]; d[i]+=rv[i]*mv[i]; } }
    if (j2) { size_t o=(size_t)(j2-1)*256+c; ld8h(msg+o, mv); ld8h(r+o, rv);
#pragma unroll
              for (int i=0;i<8;i++){ s[i]+=mv[i]; d[i]+=rv[i]*mv[i]; } }
    st8h(suv + (size_t)e * 256 + c, s);
    st8h(rd  + (size_t)e * 256 + c, d);
}

__global__ void xedge_k(const __half* __restrict__ xg, const int* __restrict__ ei,
                        __half* __restrict__ xe, int E, int Ne)
{
    int t = blockIdx.x * blockDim.x + threadIdx.x;
    if (t >= Ne * 64) return;
    int j = t >> 6, c = t & 63;      // chunk of 8 within 512
    int u = ei[2 * j], v = ei[E + 2 * j];
    int c2 = (c < 32) ? c : (c - 32);
    float a[8], b[8], o[8];
    ld8h(xg + (size_t)u * 256 + c2 * 8, a);
    ld8h(xg + (size_t)v * 256 + c2 * 8, b);
    if (c < 32) {
#pragma unroll
        for (int i = 0; i < 8; i++) o[i] = fabsf(a[i] - b[i]);
    } else {
#pragma unroll
        for (int i = 0; i < 8; i++) o[i] = a[i] + b[i];
    }
    st8h(xe + (size_t)j * 512 + c * 8, o);
}

__global__ void softmax_k(const float* __restrict__ lg, float* __restrict__ out, int T)
{
    __shared__ float red[1024];
    int t = threadIdx.x;
    float mx = -1e30f;
    for (int i = t; i < T; i += 1024) mx = fmaxf(mx, lg[i]);
    red[t] = mx; __syncthreads();
    for (int s = 512; s; s >>= 1) { if (t < s) red[t] = fmaxf(red[t], red[t + s]); __syncthreads(); }
    float m = red[0]; __syncthreads();
    float sm = 0.f;
    for (int i = t; i < T; i += 1024) sm += expf(lg[i] - m);
    red[t] = sm; __syncthreads();
    for (int s = 512; s; s >>= 1) { if (t < s) red[t] += red[t + s]; __syncthreads(); }
    float inv = 1.f / red[0];
    for (int i = t; i < T; i += 1024) out[i] = expf(lg[i] - m) * inv;
}

// ---------------------------------------------------------------------------
// Launch — fp16 GEMMs (4-stage); serial layers; fused l0 / seg-sum / heads.
// ---------------------------------------------------------------------------
extern "C" void kernel_launch(void* const* d_in, const int* in_sizes, int n_in,
                              void* d_out, int out_size)
{
    const float* x     = (const float*)d_in[0];
    const float* ea    = (const float*)d_in[1];
    const int*   ei    = (const int*)  d_in[2];
    const int*   nbr   = (const int*)  d_in[3];
    const float* Wz_w  = (const float*)d_in[4];
    const float* Wz_b  = (const float*)d_in[5];
    const float* Wr_w  = (const float*)d_in[6];
    const float* Wr_b  = (const float*)d_in[7];
    const float* W_w   = (const float*)d_in[8];
    const float* U_w   = (const float*)d_in[9];
    const float* U_b   = (const float*)d_in[10];
    const float* mlp_w = (const float*)d_in[11];
    const float* mlp_b = (const float*)d_in[12];
    const float* nc1_w = (const float*)d_in[13];
    const float* nc1_b = (const float*)d_in[14];
    const float* nc2_w = (const float*)d_in[15];
    const float* nc2_b = (const float*)d_in[16];
    const float* ec1_w = (const float*)d_in[17];
    const float* ec1_b = (const float*)d_in[18];
    const float* ec2_w = (const float*)d_in[19];
    const float* ec2_b = (const float*)d_in[20];

    const int n  = in_sizes[0] / 128;
    const int E  = in_sizes[1] / 32;
    const int Ne = E / 2;
    const int* tgt = ei + E;

    __half *feats, *suv, *zb, *rb, *rd, *msgA, *msgB, *aggr16, *x16, *xg, *xe, *wr_, *wl0;
    float *aggr, *lg, *bl0;
    cudaGetSymbolAddress((void**)&feats,  g_feats);
    cudaGetSymbolAddress((void**)&suv,    g_suv);
    cudaGetSymbolAddress((void**)&zb,     g_zbuf);
    cudaGetSymbolAddress((void**)&rb,     g_rbuf);
    cudaGetSymbolAddress((void**)&rd,     g_rd);
    cudaGetSymbolAddress((void**)&msgA,   g_msgA);
    cudaGetSymbolAddress((void**)&msgB,   g_msgB);
    cudaGetSymbolAddress((void**)&aggr,   g_aggr);
    cudaGetSymbolAddress((void**)&aggr16, g_aggr16);
    cudaGetSymbolAddress((void**)&x16,    g_x16);
    cudaGetSymbolAddress((void**)&xg,     g_xg);
    cudaGetSymbolAddress((void**)&xe,     g_xe);
    cudaGetSymbolAddress((void**)&lg,     g_logits);
    cudaGetSymbolAddress((void**)&wr_,    g_wrnd);
    cudaGetSymbolAddress((void**)&wl0,    g_wl0);
    cudaGetSymbolAddress((void**)&bl0,    g_bl0);

    static cudaStream_t s1 = nullptr;
    static cudaEvent_t  ev[16];
    if (!s1) {
        cudaStreamCreateWithFlags(&s1, cudaStreamNonBlocking);
        for (int i = 0; i < 16; i++)
            cudaEventCreateWithFlags(&ev[i], cudaEventDisableTiming);
    }

    cudaFuncSetAttribute(gemm_tc<0,160,256>, cudaFuncAttributeMaxDynamicSharedMemorySize, SMEM_BYTES);
    cudaFuncSetAttribute(gemm_tc<2,160,256>, cudaFuncAttributeMaxDynamicSharedMemorySize, SMEM_BYTES);
    cudaFuncSetAttribute(gemm_tc<5,160,256>, cudaFuncAttributeMaxDynamicSharedMemorySize, SMEM_BYTES);
    cudaFuncSetAttribute(gemm_tc<7,160,0>,   cudaFuncAttributeMaxDynamicSharedMemorySize, SMEM_BYTES);
    cudaFuncSetAttribute(gemm_tc<1,128,256>, cudaFuncAttributeMaxDynamicSharedMemorySize, SMEM_BYTES);
    cudaFuncSetAttribute(gemm_tc<6,256,0>,   cudaFuncAttributeMaxDynamicSharedMemorySize, SMEM_BYTES);
    cudaFuncSetAttribute(gemm_tc<6,512,0>,   cudaFuncAttributeMaxDynamicSharedMemorySize, SMEM_BYTES);

    const __half* rWz  = wr_ + W_OFF[0];
    const __half* rWr  = wr_ + W_OFF[1];
    const __half* rW   = wr_ + W_OFF[2];
    const __half* rU   = wr_ + W_OFF[3];
    const __half* rmlp = wr_ + W_OFF[4];
    const __half* rnc1 = wr_ + W_OFF[5];
    const __half* rec1 = wr_ + W_OFF[6];

    const int TPB = 256;
    dim3 gg(2, (E + 127) / 128);

    // ---- prologue: fork first, then s1 weight prep ----
    cudaEventRecord(ev[0], 0);
    cudaStreamWaitEvent(s1, ev[0], 0);
    roundw_k<<<dim3(416, 7), 256, 0, s1>>>(Wz_w, Wr_w, W_w, U_w, mlp_w, nc1_w, ec1_w, wr_);
    il0_k<<<80, 256, 0, s1>>>(Wz_w, W_w, Wz_b, U_b, wl0, bl0);
    cudaEventRecord(ev[1], s1);

    feats_k<<<(E * 20 + TPB - 1) / TPB, TPB>>>(x, ea, tgt, feats, E);
    f2h_k<<<(n * 16 + TPB - 1) / TPB, TPB>>>(x, x16, n * 16);
    cudaMemsetAsync(aggr, 0, (size_t)n * 256 * sizeof(float));
    initlg_k<<<(n + Ne + TPB - 1) / TPB, TPB>>>(lg, nc2_b, ec2_b, n, n + Ne);

    cudaStreamWaitEvent(0, ev[1], 0);

    // ---- layer 0: ONE fused GEMM (interleaved z/m columns) ----
    dim3 gl0(4, (E + 127) / 128);
    gemm_tc<7,160,0><<<gl0, 256, SMEM_BYTES>>>(
        feats, nullptr, wl0, 160, nullptr, 0,
        bl0, nullptr, nullptr, nullptr, nullptr, msgA, nullptr, E, 512);

    // ---- layers 1..3: serial r -> grs -> z -> m ----
    __half* msg_in  = msgA;
    __half* msg_out = msgB;
    const int gE32 = (E * 32 + TPB - 1) / TPB;
    for (int l = 1; l < 4; l++) {
        const __half* wz = rWz + (size_t)l * 256 * 416;
        const __half* wrr= rWr + (size_t)l * 256 * 416;
        const __half* ww = rW  + (size_t)l * 256 * 160;
        const __half* uw = rU  + (size_t)l * 256 * 256;

        gemm_tc<0,160,256><<<gg, 256, SMEM_BYTES>>>(
            feats, msg_in, wrr, 416, wrr + 160, 416,
            Wr_b + l * 256, nullptr, nullptr, nullptr, nullptr, rb, nullptr, E, 256);
        grs_k<<<gE32, TPB>>>(rb, msg_in, nbr, suv, rd, E);
        gemm_tc<0,160,256><<<gg, 256, SMEM_BYTES>>>(
            feats, suv, wz, 416, wz + 160, 416,
            Wz_b + l * 256, nullptr, nullptr, nullptr, nullptr, zb, nullptr, E, 256);
        if (l < 3) {
            gemm_tc<2,160,256><<<gg, 256, SMEM_BYTES>>>(
                feats, rd, ww, 160, uw, 256,
                U_b + l * 256, zb, suv, nullptr, nullptr, msg_out, nullptr, E, 256);
        } else {
            gemm_tc<5,160,256><<<gg, 256, SMEM_BYTES>>>(
                feats, rd, ww, 160, uw, 256,
                U_b + l * 256, zb, suv, nullptr, tgt, nullptr, aggr, E, 256);
        }
        __half* tmp = msg_in; msg_in = msg_out; msg_out = tmp;
    }

    // ---- readout ----
    f2h_k<<<(n * 32 + TPB - 1) / TPB, TPB>>>(aggr, aggr16, n * 32);
    dim3 gx(2, (n + 127) / 128);
    gemm_tc<1,128,256><<<gx, 256, SMEM_BYTES>>>(
        x16, aggr16, rmlp, 384, rmlp + 128, 384,
        mlp_b, nullptr, nullptr, nullptr, nullptr, xg, nullptr, n, 256);
    cudaEventRecord(ev[2], 0);
    cudaStreamWaitEvent(s1, ev[2], 0);

    // s1: edge branch (xedge + fused 512->1 dot)
    xedge_k<<<(Ne * 64 + TPB - 1) / TPB, TPB, 0, s1>>>(xg, ei, xe, E, Ne);
    dim3 g2(4, (Ne + 127) / 128);
    gemm_tc<6,512,0><<<g2, 256, SMEM_BYTES, s1>>>(
        xe, nullptr, rec1, 512, nullptr, 0,
        ec1_b, nullptr, nullptr, ec2_w, nullptr, nullptr, lg + n, Ne, 512);
    cudaEventRecord(ev[3], s1);

    // s0: node branch (fused 512->1 dot)
    dim3 g1(4, (n + 127) / 128);
    gemm_tc<6,256,0><<<g1, 256, SMEM_BYTES>>>(
        xg, nullptr, rnc1, 256, nullptr, 0,
        nc1_b, nullptr, nullptr, nc2_w, nullptr, nullptr, lg, n, 512);

    // join + softmax
    cudaStreamWaitEvent(0, ev[3], 0);
    softmax_k<<<1, 1024>>>(lg, (float*)d_out, n + Ne);
}